// round 13
// baseline (speedup 1.0000x reference)
#include <cuda_runtime.h>
#include <cuda_bf16.h>
#include <math.h>
#include <stdint.h>

// Problem constants
#define BB 4
#define SS 1024
#define DD 512
#define EE 8
#define HH 1536
#define TT (BB*SS)          // 4096 tokens
#define SIXD (6*DD)         // 3072

// ---------------- scratch (device globals; no runtime allocation) ----------------
#define OF_MODS 0                            // B*6D
#define OF_H    (OF_MODS + BB*SIXD)          // T*D
#define OF_Q    (OF_H  + TT*DD)
#define OF_K    (OF_Q  + TT*DD)
#define OF_V    (OF_K  + TT*DD)
#define OF_SC   (OF_V  + TT*DD)              // B*D*D
#define OF_AT   (OF_SC + BB*DD*DD)           // T*D
#define OF_AO   (OF_AT + TT*DD)
#define OF_XM   (OF_AO + TT*DD)
#define OF_LG   (OF_XM + TT*DD)              // T*E
#define OF_PR   (OF_LG + TT*EE)              // T*E
#define OF_NRM  (OF_PR + TT*EE)              // B*E
#define OF_WT   (OF_NRM + BB*EE)             // E*T
#define OF_QS   (OF_WT + EE*TT)              // T*2 (q stats)
#define OF_KS   (OF_QS + 2*TT)               // T*2 (k stats)
#define OF_G    (OF_KS + 2*TT)               // 2T*H
#define OF_W1T  (OF_G + 2*TT*HH)             // E*H*D
#define OF_W3T  (OF_W1T + EE*HH*DD)
#define OF_W2T  (OF_W3T + EE*HH*DD)          // E*D*H
#define OF_WQKVT (OF_W2T + EE*DD*HH)         // 1536*512
#define OF_WOT  (OF_WQKVT + 3*DD*DD)         // D*D
#define OF_QT   (OF_WOT + DD*DD)             // B*D*S
#define OF_KT   (OF_QT + TT*DD)              // B*D*S
#define BUF_TOTAL (OF_KT + TT*DD)

__device__ __align__(256) float g_buf[BUF_TOTAL];

// int scratch: cnt(8) off(8) tok(E*T)
#define IOF_CNT 0
#define IOF_OFF 8
#define IOF_TOK 16
__device__ int g_ibuf[IOF_TOK + EE*TT];

// ---------------- helpers ----------------
__device__ __forceinline__ uint32_t f2tf32(float f) {
    uint32_t r;
    asm("cvt.rna.tf32.f32 %0, %1;" : "=r"(r) : "f"(f));
    return r;
}
__device__ __forceinline__ float f2tf32f(float f) {
    return __uint_as_float(f2tf32(f));
}
__device__ __forceinline__ void mma16n8k8(float* d, const uint32_t* a, const uint32_t* b) {
    asm volatile(
        "mma.sync.aligned.m16n8k8.row.col.f32.tf32.tf32.f32 "
        "{%0,%1,%2,%3}, {%4,%5,%6,%7}, {%8,%9}, {%0,%1,%2,%3};"
        : "+f"(d[0]), "+f"(d[1]), "+f"(d[2]), "+f"(d[3])
        : "r"(a[0]), "r"(a[1]), "r"(a[2]), "r"(a[3]), "r"(b[0]), "r"(b[1]));
}
__device__ __forceinline__ void mma16n8k16bf(float* d, const uint32_t* a, const uint32_t* b) {
    asm volatile(
        "mma.sync.aligned.m16n8k16.row.col.f32.bf16.bf16.f32 "
        "{%0,%1,%2,%3}, {%4,%5,%6,%7}, {%8,%9}, {%0,%1,%2,%3};"
        : "+f"(d[0]), "+f"(d[1]), "+f"(d[2]), "+f"(d[3])
        : "r"(a[0]), "r"(a[1]), "r"(a[2]), "r"(a[3]), "r"(b[0]), "r"(b[1]));
}
__device__ __forceinline__ void split2(float x, float y, uint32_t& hi, uint32_t& lo) {
    __nv_bfloat16 hx = __float2bfloat16_rn(x);
    __nv_bfloat16 hy = __float2bfloat16_rn(y);
    float rx = x - __bfloat162float(hx);
    float ry = y - __bfloat162float(hy);
    __nv_bfloat162 h2; h2.x = hx; h2.y = hy;
    __nv_bfloat162 l2; l2.x = __float2bfloat16_rn(rx); l2.y = __float2bfloat16_rn(ry);
    hi = *(uint32_t*)&h2;
    lo = *(uint32_t*)&l2;
}

// ---------------- elementwise / small kernels ----------------

__global__ void zero_kernel(float* out, float* scores, int* cnt) {
    int i = blockIdx.x * 256 + threadIdx.x;
    if (i < TT*DD) out[i] = 0.f;
    if (i < BB*DD*DD) scores[i] = 0.f;
    if (i < EE) cnt[i] = 0;
}

__global__ void mods_kernel(const float* __restrict__ c,
                            const float* __restrict__ W_ada,
                            const float* __restrict__ b_ada,
                            float* __restrict__ mods) {
    int b   = blockIdx.x;
    int col = blockIdx.y * 256 + threadIdx.x;
    __shared__ float sc[DD];
    for (int i = threadIdx.x; i < DD; i += 256) {
        float v = c[b*DD + i];
        sc[i] = v / (1.f + expf(-v));
    }
    __syncthreads();
    float a0 = 0.f, a1 = 0.f, a2 = 0.f, a3 = 0.f;
    for (int d = 0; d < DD; d += 4) {
        a0 += sc[d+0] * W_ada[(size_t)(d+0)*SIXD + col];
        a1 += sc[d+1] * W_ada[(size_t)(d+1)*SIXD + col];
        a2 += sc[d+2] * W_ada[(size_t)(d+2)*SIXD + col];
        a3 += sc[d+3] * W_ada[(size_t)(d+3)*SIXD + col];
    }
    mods[b*SIXD + col] = b_ada[col] + ((a0 + a1) + (a2 + a3));
}

// 2 rows/block, shfl reduction.
template<bool RES>
__global__ void ln_mod_kernel(const float* __restrict__ in, const float* __restrict__ ao,
                              float* __restrict__ out,
                              const float* __restrict__ w, const float* __restrict__ bb,
                              const float* __restrict__ mods, int sh_ofs, int sc_ofs) {
    int half = threadIdx.x >> 7;
    int t    = threadIdx.x & 127;
    int row  = blockIdx.x * 2 + half;
    int bat  = row >> 10;
    const float* x = in + (size_t)row * DD;
    const float* mrow = mods + bat * SIXD;
    float v0 = x[t], v1 = x[t + 128], v2 = x[t + 256], v3 = x[t + 384];
    if (RES) {
        const float* a = ao + (size_t)row * DD;
        v0 += mrow[2*DD + t]       * a[t];
        v1 += mrow[2*DD + t + 128] * a[t + 128];
        v2 += mrow[2*DD + t + 256] * a[t + 256];
        v3 += mrow[2*DD + t + 384] * a[t + 384];
    }
    __shared__ float part[2][4];
    __shared__ float stat[2][2];
    int wsub = (threadIdx.x >> 5) & 3;
    int lane = threadIdx.x & 31;
    float s = (v0 + v1) + (v2 + v3);
    #pragma unroll
    for (int o = 16; o; o >>= 1) s += __shfl_down_sync(0xffffffffu, s, o);
    if (!lane) part[half][wsub] = s;
    __syncthreads();
    if (t == 0)
        stat[half][0] = ((part[half][0] + part[half][1]) + (part[half][2] + part[half][3])) * (1.f / DD);
    __syncthreads();
    float m = stat[half][0];
    float d0 = v0 - m, d1 = v1 - m, d2 = v2 - m, d3 = v3 - m;
    float qq = (d0*d0 + d1*d1) + (d2*d2 + d3*d3);
    #pragma unroll
    for (int o = 16; o; o >>= 1) qq += __shfl_down_sync(0xffffffffu, qq, o);
    if (!lane) part[half][wsub] = qq;
    __syncthreads();
    if (t == 0)
        stat[half][1] = rsqrtf(((part[half][0] + part[half][1]) + (part[half][2] + part[half][3])) * (1.f / DD) + 1e-5f);
    __syncthreads();
    float inv = stat[half][1];
    float* op = out + (size_t)row * DD;
    #pragma unroll
    for (int j = 0; j < 4; j++) {
        int i = t + j * 128;
        float dd = (j == 0 ? d0 : j == 1 ? d1 : j == 2 ? d2 : d3);
        float y = dd * inv * w[i] + bb[i];
        op[i] = y * (1.f + mrow[sc_ofs + i]) + mrow[sh_ofs + i];
    }
}

// per-row LN stats only: stat[row] = (mean, rsqrt(var+eps)). 2 rows/block.
__global__ void row_stats_kernel(const float* __restrict__ a, float2* __restrict__ st) {
    int half = threadIdx.x >> 7;
    int t    = threadIdx.x & 127;
    int row  = blockIdx.x * 2 + half;
    const float* x = a + (size_t)row * DD;
    float v0 = x[t], v1 = x[t + 128], v2 = x[t + 256], v3 = x[t + 384];
    __shared__ float part[2][4];
    __shared__ float mean_s[2];
    int wsub = (threadIdx.x >> 5) & 3;
    int lane = threadIdx.x & 31;
    float s = (v0 + v1) + (v2 + v3);
    #pragma unroll
    for (int o = 16; o; o >>= 1) s += __shfl_down_sync(0xffffffffu, s, o);
    if (!lane) part[half][wsub] = s;
    __syncthreads();
    if (t == 0)
        mean_s[half] = ((part[half][0] + part[half][1]) + (part[half][2] + part[half][3])) * (1.f / DD);
    __syncthreads();
    float m = mean_s[half];
    float d0 = v0 - m, d1 = v1 - m, d2 = v2 - m, d3 = v3 - m;
    float qq = (d0*d0 + d1*d1) + (d2*d2 + d3*d3);
    #pragma unroll
    for (int o = 16; o; o >>= 1) qq += __shfl_down_sync(0xffffffffu, qq, o);
    if (!lane) part[half][wsub] = qq;
    __syncthreads();
    if (t == 0) {
        float inv = rsqrtf(((part[half][0] + part[half][1]) + (part[half][2] + part[half][3])) * (1.f / DD) + 1e-5f);
        st[row] = make_float2(m, inv);
    }
}

// fused LN-apply + transpose: dst[b][d][s] = (src[b][s][d]-m_s)*inv_s*w[d]+b[d].
__global__ void transpose_ln_kernel(const float* __restrict__ qsrc, const float* __restrict__ ksrc,
                                    float* __restrict__ qdst, float* __restrict__ kdst,
                                    const float2* __restrict__ qst, const float2* __restrict__ kst,
                                    const float* __restrict__ qw, const float* __restrict__ qb,
                                    const float* __restrict__ kw, const float* __restrict__ kb) {
    __shared__ float tbuf[32][33];
    __shared__ float2 sst[32];
    int z = blockIdx.z;
    bool isK = (z >= BB);
    int b = isK ? z - BB : z;
    const float* src = (isK ? ksrc : qsrc) + (size_t)b * SS * DD;
    float* dst       = (isK ? kdst : qdst) + (size_t)b * DD * SS;
    const float2* st = (isK ? kst : qst) + b * SS;
    const float* w   = isK ? kw : qw;
    const float* bbv = isK ? kb : qb;
    int d0 = blockIdx.x * 32;
    int s0 = blockIdx.y * 32;
    int x = threadIdx.x, y = threadIdx.y;
    if (threadIdx.y == 0) sst[x] = st[s0 + x];
    __syncthreads();
    float wv = w[d0 + x], bv = bbv[d0 + x];
    #pragma unroll
    for (int j = 0; j < 32; j += 8) {
        float v = src[(size_t)(s0 + y + j) * DD + d0 + x];
        float2 ms = sst[y + j];
        tbuf[y + j][x] = (v - ms.x) * ms.y * wv + bv;
    }
    __syncthreads();
    #pragma unroll
    for (int j = 0; j < 32; j += 8)
        dst[(size_t)(d0 + y + j) * SS + s0 + x] = tbuf[x][y + j];
}

// softmax over rows of 512; 2 rows/block, shfl; output pre-rounded to tf32
__global__ void softmax512_kernel(float* __restrict__ a) {
    int half = threadIdx.x >> 7;
    int t    = threadIdx.x & 127;
    float* row = a + (size_t)(blockIdx.x * 2 + half) * DD;
    float v0 = row[t], v1 = row[t + 128], v2 = row[t + 256], v3 = row[t + 384];
    __shared__ float part[2][4];
    __shared__ float stat[2];
    int wsub = (threadIdx.x >> 5) & 3;
    int lane = threadIdx.x & 31;
    float mx = fmaxf(fmaxf(v0, v1), fmaxf(v2, v3));
    #pragma unroll
    for (int o = 16; o; o >>= 1) mx = fmaxf(mx, __shfl_down_sync(0xffffffffu, mx, o));
    if (!lane) part[half][wsub] = mx;
    __syncthreads();
    if (t == 0)
        stat[half] = fmaxf(fmaxf(part[half][0], part[half][1]), fmaxf(part[half][2], part[half][3]));
    __syncthreads();
    float m = stat[half];
    float e0 = expf(v0 - m), e1 = expf(v1 - m), e2 = expf(v2 - m), e3 = expf(v3 - m);
    float s = (e0 + e1) + (e2 + e3);
    #pragma unroll
    for (int o = 16; o; o >>= 1) s += __shfl_down_sync(0xffffffffu, s, o);
    if (!lane) part[half][wsub] = s;
    __syncthreads();
    if (t == 0)
        stat[half] = 1.f / ((part[half][0] + part[half][1]) + (part[half][2] + part[half][3]));
    __syncthreads();
    float inv = stat[half];
    row[t]       = f2tf32f(e0 * inv);
    row[t + 128] = f2tf32f(e1 * inv);
    row[t + 256] = f2tf32f(e2 * inv);
    row[t + 384] = f2tf32f(e3 * inv);
}

__global__ void logits_kernel(const float* __restrict__ xm, const float* __restrict__ Wr,
                              const float* __restrict__ br, float* __restrict__ logits) {
    int t = blockIdx.x;
    __shared__ float s[DD];
    for (int i = threadIdx.x; i < DD; i += 256) s[i] = xm[(size_t)t*DD + i];
    __syncthreads();
    int w = threadIdx.x >> 5, lane = threadIdx.x & 31;
    float acc = 0.f;
    for (int d = lane; d < DD; d += 32) acc += s[d] * Wr[d*EE + w];
    for (int o = 16; o; o >>= 1) acc += __shfl_down_sync(0xffffffffu, acc, o);
    if (!lane) logits[t*EE + w] = acc + br[w];
}

__global__ void nrm_kernel(const float* __restrict__ logits, float* __restrict__ nrm) {
    int be = blockIdx.x, b = be >> 3, e = be & 7;
    int tid = threadIdx.x;
    float s = 0.f;
    for (int si = tid; si < SS; si += 256) {
        float v = logits[(size_t)((b << 10) + si)*EE + e];
        s += v * v;
    }
    __shared__ float red[256];
    red[tid] = s; __syncthreads();
    for (int o = 128; o; o >>= 1) { if (tid < o) red[tid] += red[tid + o]; __syncthreads(); }
    if (!tid) nrm[be] = sqrtf(red[0]);
}

__global__ void route_kernel(const float* __restrict__ logits, const float* __restrict__ nrm,
                             float* __restrict__ probs, int* __restrict__ cnt,
                             int* __restrict__ tokl, float* __restrict__ wtl) {
    int t = blockIdx.x * 128 + threadIdx.x;
    if (t >= TT) return;
    int b = t >> 10;
    float l[EE];
    float mx = -1e30f;
    #pragma unroll
    for (int e = 0; e < EE; e++) {
        l[e] = logits[t*EE + e] / fmaxf(nrm[b*EE + e], 1e-12f);
        mx = fmaxf(mx, l[e]);
    }
    float sum = 0.f;
    #pragma unroll
    for (int e = 0; e < EE; e++) { l[e] = expf(l[e] - mx); sum += l[e]; }
    float inv = 1.f / sum;
    #pragma unroll
    for (int e = 0; e < EE; e++) { l[e] *= inv; probs[t*EE + e] = l[e]; }
    int i0 = 0;
    #pragma unroll
    for (int e = 1; e < EE; e++) if (l[e] > l[i0]) i0 = e;
    int i1 = -1;
    #pragma unroll
    for (int e = 0; e < EE; e++) {
        if (e == i0) continue;
        if (i1 < 0 || l[e] > l[i1]) i1 = e;
    }
    int p0 = atomicAdd(&cnt[i0], 1);
    tokl[i0*TT + p0] = t; wtl[i0*TT + p0] = l[i0];
    int p1 = atomicAdd(&cnt[i1], 1);
    tokl[i1*TT + p1] = t; wtl[i1*TT + p1] = l[i1];
}

__global__ void offsets_kernel(const int* __restrict__ cnt, int* __restrict__ off) {
    if (threadIdx.x == 0) {
        int a = 0;
        for (int e = 0; e < EE; e++) { off[e] = a; a += cnt[e]; }
    }
}

// 32x32 tiled transpose, per z-slice.  RND: pre-round to tf32.
template<bool RND>
__global__ void transpose_kernel(const float* __restrict__ src, float* __restrict__ dst,
                                 int R, int C) {
    __shared__ float t[32][33];
    size_t eb = (size_t)blockIdx.z * R * C;
    int c0 = blockIdx.x * 32, r0 = blockIdx.y * 32;
    int x = threadIdx.x, y = threadIdx.y;
    #pragma unroll
    for (int j = 0; j < 32; j += 8) {
        float v = src[eb + (size_t)(r0 + y + j) * C + c0 + x];
        t[y + j][x] = RND ? f2tf32f(v) : v;
    }
    __syncthreads();
    #pragma unroll
    for (int j = 0; j < 32; j += 8)
        dst[eb + (size_t)(c0 + y + j) * R + r0 + x] = t[x][y + j];
}

// merged 4x DxD transpose: z=0..3 -> Wq,Wk,Wv (no round) | Wo (rounded)
__global__ void transpose4_kernel(const float* __restrict__ Wq, const float* __restrict__ Wk,
                                  const float* __restrict__ Wv, const float* __restrict__ Wo,
                                  float* __restrict__ wqkvt, float* __restrict__ wot) {
    __shared__ float t[32][33];
    int z = blockIdx.z;
    const float* src = (z == 0) ? Wq : (z == 1) ? Wk : (z == 2) ? Wv : Wo;
    float* dst = (z == 3) ? wot : (wqkvt + (size_t)z * DD * DD);
    bool rnd = (z == 3);
    int c0 = blockIdx.x * 32, r0 = blockIdx.y * 32;
    int x = threadIdx.x, y = threadIdx.y;
    #pragma unroll
    for (int j = 0; j < 32; j += 8) {
        float v = src[(size_t)(r0 + y + j) * DD + c0 + x];
        t[y + j][x] = rnd ? f2tf32f(v) : v;
    }
    __syncthreads();
    #pragma unroll
    for (int j = 0; j < 32; j += 8)
        dst[(size_t)(c0 + y + j) * DD + r0 + x] = t[x][y + j];
}

// dual transpose: W1 & W3 in one pass, pre-rounded to tf32
__global__ void transpose13_kernel(const float* __restrict__ s1, const float* __restrict__ s3,
                                   float* __restrict__ d1, float* __restrict__ d3,
                                   int R, int C) {
    __shared__ float t1[32][33];
    __shared__ float t3[32][33];
    size_t eb = (size_t)blockIdx.z * R * C;
    int c0 = blockIdx.x * 32, r0 = blockIdx.y * 32;
    int x = threadIdx.x, y = threadIdx.y;
    #pragma unroll
    for (int j = 0; j < 32; j += 8) {
        size_t si = eb + (size_t)(r0 + y + j) * C + c0 + x;
        t1[y + j][x] = f2tf32f(s1[si]);
        t3[y + j][x] = f2tf32f(s3[si]);
    }
    __syncthreads();
    #pragma unroll
    for (int j = 0; j < 32; j += 8) {
        size_t di = eb + (size_t)(c0 + y + j) * R + r0 + x;
        d1[di] = t1[x][y + j];
        d3[di] = t3[x][y + j];
    }
}

// ============ bf16 3-pass "fp32-equivalent" GEMM: C = A @ Bt^T ============
// ldAB = row stride of A and Bt (k-dim stride). K = loop extent.
// MODE 1: QKV split write (V pre-rounded to tf32).
// MODE 2: split-K scores: z = b*2+split; k-offset split*K; epilogue atomicAdd.
template<int MODE, int NI>
__global__ void __launch_bounds__(256, 2)
b163_gemm_kernel(const float* __restrict__ A, const float* __restrict__ Bt,
                 float* __restrict__ C, int K, int N, int ldAB,
                 size_t sA, size_t sB, size_t sC,
                 float* __restrict__ Qo, float* __restrict__ Ko, float* __restrict__ Vo) {
    constexpr int NT = NI * 16;
    __shared__ uint32_t Ah[128][12], Al[128][12];
    __shared__ uint32_t Bh[NT][12],  Bl[NT][12];

    const int tid = threadIdx.x;
    const int n0 = blockIdx.x * NT;
    const int m0 = blockIdx.y * 128;
    if (MODE == 2) {
        int b = blockIdx.z >> 1, split = blockIdx.z & 1;
        A += b * sA + (size_t)split * K;
        Bt += b * sB + (size_t)split * K;
        C += b * sC;
    }

    const int wid = tid >> 5, lid = tid & 31;
    const int w_m = (wid & 3) * 32, w_n = (wid >> 2) * (NI * 8);
    const int lq = lid >> 2, lr = lid & 3;
    const int rowA = tid >> 1, cA = (tid & 1) * 8;
    const int rowB = (NI == 8) ? (tid >> 1) : (tid >> 2);
    const int cB   = (NI == 8) ? ((tid & 1) * 8) : ((tid & 3) * 4);

    float acc[2][NI][4];
    #pragma unroll
    for (int i = 0; i < 2; i++)
        #pragma unroll
        for (int j = 0; j < NI; j++)
            #pragma unroll
            for (int l = 0; l < 4; l++) acc[i][j][l] = 0.f;

    float4 ra0, ra1, rb0, rb1;
    auto LDG = [&](int t) {
        const float* ap = A + (size_t)(m0 + rowA) * ldAB + t*16 + cA;
        ra0 = *(const float4*)ap; ra1 = *(const float4*)(ap + 4);
        const float* bp = Bt + (size_t)(n0 + rowB) * ldAB + t*16 + cB;
        rb0 = *(const float4*)bp;
        if (NI == 8) rb1 = *(const float4*)(bp + 4);
    };

    const int NK = K / 16;
    LDG(0);
    for (int i = 0; i < NK; i++) {
        {
            uint32_t* aph = &Ah[rowA][cA/2];
            uint32_t* apl = &Al[rowA][cA/2];
            split2(ra0.x, ra0.y, aph[0], apl[0]);
            split2(ra0.z, ra0.w, aph[1], apl[1]);
            split2(ra1.x, ra1.y, aph[2], apl[2]);
            split2(ra1.z, ra1.w, aph[3], apl[3]);
            uint32_t* bph = &Bh[rowB][cB/2];
            uint32_t* bpl = &Bl[rowB][cB/2];
            split2(rb0.x, rb0.y, bph[0], bpl[0]);
            split2(rb0.z, rb0.w, bph[1], bpl[1]);
            if (NI == 8) {
                split2(rb1.x, rb1.y, bph[2], bpl[2]);
                split2(rb1.z, rb1.w, bph[3], bpl[3]);
            }
        }
        __syncthreads();
        if (i + 1 < NK) LDG(i + 1);
        uint32_t ah[2][4], al[2][4];
        #pragma unroll
        for (int mi = 0; mi < 2; mi++) {
            int mr = w_m + mi*16 + lq;
            ah[mi][0] = Ah[mr    ][lr];     al[mi][0] = Al[mr    ][lr];
            ah[mi][1] = Ah[mr + 8][lr];     al[mi][1] = Al[mr + 8][lr];
            ah[mi][2] = Ah[mr    ][4 + lr]; al[mi][2] = Al[mr    ][4 + lr];
            ah[mi][3] = Ah[mr + 8][4 + lr]; al[mi][3] = Al[mr + 8][4 + lr];
        }
        #pragma unroll
        for (int ni = 0; ni < NI; ni++) {
            int nr = w_n + ni*8 + lq;
            uint32_t bh[2], bl[2];
            bh[0] = Bh[nr][lr]; bh[1] = Bh[nr][4 + lr];
            bl[0] = Bl[nr][lr]; bl[1] = Bl[nr][4 + lr];
            mma16n8k16bf(acc[0][ni], ah[0], bh);
            mma16n8k16bf(acc[1][ni], ah[1], bh);
            mma16n8k16bf(acc[0][ni], ah[0], bl);
            mma16n8k16bf(acc[1][ni], ah[1], bl);
            mma16n8k16bf(acc[0][ni], al[0], bh);
            mma16n8k16bf(acc[1][ni], al[1], bh);
        }
        __syncthreads();
    }

    float* base = C;
    int csub = 0;
    bool isV = false;
    if (MODE == 1) {
        if (n0 < 512)       { base = Qo; csub = 0; }
        else if (n0 < 1024) { base = Ko; csub = 512; }
        else                { base = Vo; csub = 1024; isV = true; }
    }
    #pragma unroll
    for (int mi = 0; mi < 2; mi++) {
        #pragma unroll
        for (int half = 0; half < 2; half++) {
            int r = w_m + mi*16 + lq + half*8;
            #pragma unroll
            for (int ni = 0; ni < NI; ni++) {
                float v0 = acc[mi][ni][half*2 + 0];
                float v1 = acc[mi][ni][half*2 + 1];
                int col = w_n + ni*8 + 2*lr;
                if (MODE == 2) {
                    float* cp = C + (size_t)(m0 + r) * N + n0 + col;
                    atomicAdd(cp + 0, v0);
                    atomicAdd(cp + 1, v1);
                } else {
                    float* cp = base + (size_t)(m0 + r) * DD + (n0 - csub) + col;
                    if (isV) { cp[0] = f2tf32f(v0); cp[1] = f2tf32f(v1); }
                    else     { cp[0] = v0;          cp[1] = v1; }
                }
            }
        }
    }
}

// ============ tf32 mma.sync GEMM: pre-rounded inputs, raw bit copy ============
template<int MODE, int NI, bool CVTOUT>
__global__ void __launch_bounds__(256, 2)
tf32_gemm_kernel(const float* __restrict__ A, const float* __restrict__ Bt,
                 float* __restrict__ C, int K, int N, int ldA,
                 size_t sA, size_t sB, size_t sC,
                 const int* __restrict__ cnt, const int* __restrict__ off,
                 const int* __restrict__ tokl, const float* __restrict__ wtl) {
    constexpr int NT = NI * 16;
    __shared__ uint32_t As[128][36];
    __shared__ uint32_t Bs[NT][36];
    __shared__ int stok[128];
    __shared__ float swt[128];

    const int tid = threadIdx.x;
    const int n0 = blockIdx.x * NT;
    int m0 = 0, count = 0, t0 = 0, gbase = 0;

    if (MODE == 0) {
        m0 = blockIdx.y * 128;
        A += blockIdx.z * sA; Bt += blockIdx.z * sB; C += blockIdx.z * sC;
    } else {
        const int e = blockIdx.z;
        count = cnt[e];
        t0 = blockIdx.y * 128;
        if (t0 >= count) return;
        gbase = off[e] + t0;
        if (tid < 128) {
            bool ok = (t0 + tid) < count;
            stok[tid] = ok ? tokl[e*TT + t0 + tid] : -1;
            swt[tid]  = ok ? wtl [e*TT + t0 + tid] : 0.f;
        }
        Bt += (size_t)e * N * K;
        __syncthreads();
    }

    const int wid = tid >> 5, lid = tid & 31;
    const int w_m = (wid & 3) * 32, w_n = (wid >> 2) * (NI * 8);
    const int lq = lid >> 2, lr = lid & 3;
    const int row_l = tid >> 3, c4 = tid & 7;

    float acc[2][NI][4];
    #pragma unroll
    for (int i = 0; i < 2; i++)
        #pragma unroll
        for (int j = 0; j < NI; j++)
            #pragma unroll
            for (int l = 0; l < 4; l++) acc[i][j][l] = 0.f;

    float4 ra[4], rb[NI/2];
    auto LDG = [&](int t) {
        #pragma unroll
        for (int j = 0; j < 4; j++) {
            int row = row_l + j * 32;
            if (MODE == 0) {
                ra[j] = *(const float4*)(A + (size_t)(m0 + row) * ldA + t*32 + c4*4);
            } else {
                ra[j] = make_float4(0.f,0.f,0.f,0.f);
                if (t0 + row < count)
                    ra[j] = *(const float4*)(A + (size_t)(gbase + row) * K + t*32 + c4*4);
            }
        }
        #pragma unroll
        for (int j = 0; j < NI/2; j++) {
            int row = row_l + j * 32;
            rb[j] = *(const float4*)(Bt + (size_t)(n0 + row) * K + t*32 + c4*4);
        }
    };

    const int NK = K / 32;
    LDG(0);
    for (int i = 0; i < NK; i++) {
        #pragma unroll
        for (int j = 0; j < 4; j++) {
            int row = row_l + j * 32;
            uint32_t* ap = &As[row][c4*4];
            ap[0] = __float_as_uint(ra[j].x); ap[1] = __float_as_uint(ra[j].y);
            ap[2] = __float_as_uint(ra[j].z); ap[3] = __float_as_uint(ra[j].w);
        }
        #pragma unroll
        for (int j = 0; j < NI/2; j++) {
            int row = row_l + j * 32;
            uint32_t* bp = &Bs[row][c4*4];
            bp[0] = __float_as_uint(rb[j].x); bp[1] = __float_as_uint(rb[j].y);
            bp[2] = __float_as_uint(rb[j].z); bp[3] = __float_as_uint(rb[j].w);
        }
        __syncthreads();
        if (i + 1 < NK) LDG(i + 1);
        #pragma unroll
        for (int ks = 0; ks < 32; ks += 8) {
            uint32_t af[2][4], bf[NI][2];
            #pragma unroll
            for (int mi = 0; mi < 2; mi++) {
                int mr = w_m + mi*16 + lq;
                af[mi][0] = As[mr    ][ks + lr];
                af[mi][1] = As[mr + 8][ks + lr];
                af[mi][2] = As[mr    ][ks + 4 + lr];
                af[mi][3] = As[mr + 8][ks + 4 + lr];
            }
            #pragma unroll
            for (int ni = 0; ni < NI; ni++) {
                int nr = w_n + ni*8 + lq;
                bf[ni][0] = Bs[nr][ks + lr];
                bf[ni][1] = Bs[nr][ks + 4 + lr];
            }
            #pragma unroll
            for (int mi = 0; mi < 2; mi++)
                #pragma unroll
                for (int ni = 0; ni < NI; ni++)
                    mma16n8k8(acc[mi][ni], af[mi], bf[ni]);
        }
        __syncthreads();
    }

    #pragma unroll
    for (int mi = 0; mi < 2; mi++) {
        #pragma unroll
        for (int half = 0; half < 2; half++) {
            int r = w_m + mi*16 + lq + half*8;
            #pragma unroll
            for (int ni = 0; ni < NI; ni++) {
                float v0 = acc[mi][ni][half*2 + 0];
                float v1 = acc[mi][ni][half*2 + 1];
                int col = w_n + ni*8 + 2*lr;
                if (MODE == 0) {
                    float* cp = C + (size_t)(m0 + r) * N + n0 + col;
                    if (CVTOUT) { cp[0] = f2tf32f(v0); cp[1] = f2tf32f(v1); }
                    else        { cp[0] = v0;          cp[1] = v1; }
                } else {
                    if (t0 + r < count) {
                        int tk = stok[r];
                        float wt = swt[r];
                        float* op = C + (size_t)tk * DD + n0 + col;
                        atomicAdd(op + 0, wt * v0);
                        atomicAdd(op + 1, wt * v1);
                    }
                }
            }
        }
    }
}

// ============ fused MoE up: G = sin(xm@W1t^T) * (xm@W3t^T) ============
#define FUP_SMEM (3 * 128 * 36 * 4)
__global__ void __launch_bounds__(256)
moe_up_fused_kernel(const float* __restrict__ xm,
                    const float* __restrict__ B1t, const float* __restrict__ B3t,
                    float* __restrict__ G,
                    const int* __restrict__ cnt, const int* __restrict__ off,
                    const int* __restrict__ tokl) {
    extern __shared__ uint32_t dsm[];
    typedef uint32_t Row[36];
    Row* As  = (Row*)(dsm);
    Row* B1s = (Row*)(dsm + 128*36);
    Row* B3s = (Row*)(dsm + 2*128*36);
    __shared__ int stok[128];

    const int tid = threadIdx.x;
    const int e = blockIdx.z;
    const int count = cnt[e];
    const int t0 = blockIdx.y * 128;
    if (t0 >= count) return;
    const int n0 = blockIdx.x * 128;
    const int gbase = off[e] + t0;
    if (tid < 128)
        stok[tid] = (t0 + tid < count) ? tokl[e*TT + t0 + tid] : -1;
    B1t += (size_t)e * HH * DD;
    B3t += (size_t)e * HH * DD;
    __syncthreads();

    const int wid = tid >> 5, lid = tid & 31;
    const int w_m = (wid & 3) * 32, w_n = (wid >> 2) * 64;
    const int lq = lid >> 2, lr = lid & 3;
    const int row_l = tid >> 3, c4 = tid & 7;

    float acc1[2][8][4], acc3[2][8][4];
    #pragma unroll
    for (int i = 0; i < 2; i++)
        #pragma unroll
        for (int j = 0; j < 8; j++)
            #pragma unroll
            for (int l = 0; l < 4; l++) { acc1[i][j][l] = 0.f; acc3[i][j][l] = 0.f; }

    float4 ra[4], rb1[4], rb3[4];
    auto LDG = [&](int t) {
        #pragma unroll
        for (int j = 0; j < 4; j++) {
            int row = row_l + j * 32;
            int tk = stok[row];
            ra[j] = make_float4(0.f,0.f,0.f,0.f);
            if (tk >= 0)
                ra[j] = *(const float4*)(xm + (size_t)tk * DD + t*32 + c4*4);
            rb1[j] = *(const float4*)(B1t + (size_t)(n0 + row) * DD + t*32 + c4*4);
            rb3[j] = *(const float4*)(B3t + (size_t)(n0 + row) * DD + t*32 + c4*4);
        }
    };

    const int NK = DD / 32;
    LDG(0);
    for (int i = 0; i < NK; i++) {
        #pragma unroll
        for (int j = 0; j < 4; j++) {
            int row = row_l + j * 32;
            uint32_t* ap  = &As[row][c4*4];
            uint32_t* b1p = &B1s[row][c4*4];
            uint32_t* b3p = &B3s[row][c4*4];
            ap[0]  = f2tf32(ra[j].x);  ap[1]  = f2tf32(ra[j].y);
            ap[2]  = f2tf32(ra[j].z);  ap[3]  = f2tf32(ra[j].w);
            b1p[0] = __float_as_uint(rb1[j].x); b1p[1] = __float_as_uint(rb1[j].y);
            b1p[2] = __float_as_uint(rb1[j].z); b1p[3] = __float_as_uint(rb1[j].w);
            b3p[0] = __float_as_uint(rb3[j].x); b3p[1] = __float_as_uint(rb3[j].y);
            b3p[2] = __float_as_uint(rb3[j].z); b3p[3] = __float_as_uint(rb3[j].w);
        }
        __syncthreads();
        if (i + 1 < NK) LDG(i + 1);
        #pragma unroll
        for (int ks = 0; ks < 32; ks += 8) {
            uint32_t af[2][4];
            #pragma unroll
            for (int mi = 0; mi < 2; mi++) {
                int mr = w_m + mi*16 + lq;
                af[mi][0] = As[mr    ][ks + lr];
                af[mi][1] = As[mr + 8][ks + lr];
                af[mi][2] = As[mr    ][ks + 4 + lr];
                af[mi][3] = As[mr + 8][ks + 4 + lr];
            }
            #pragma unroll
            for (int ni = 0; ni < 8; ni++) {
                int nr = w_n + ni*8 + lq;
                uint32_t b1[2], b3[2];
                b1[0] = B1s[nr][ks + lr]; b1[1] = B1s[nr][ks + 4 + lr];
                b3[0] = B3s[nr][ks + lr]; b3[1] = B3s[nr][ks + 4 + lr];
                mma16n8k8(acc1[0][ni], af[0], b1);
                mma16n8k8(acc1[1][ni], af[1], b1);
                mma16n8k8(acc3[0][ni], af[0], b3);
                mma16n8k8(acc3[1][ni], af[1], b3);
            }
        }
        __syncthreads();
    }

    #pragma unroll
    for (int mi = 0; mi < 2; mi++) {
        #pragma unroll
        for (int half = 0; half < 2; half++) {
            int r = w_m + mi*16 + lq + half*8;
            if (t0 + r < count) {
                float* gp = G + (size_t)(gbase + r) * HH + n0;
                #pragma unroll
                for (int ni = 0; ni < 8; ni++) {
                    int col = w_n + ni*8 + 2*lr;
                    gp[col + 0] = f2tf32f(sinf(acc1[mi][ni][half*2 + 0]) * acc3[mi][ni][half*2 + 0]);
                    gp[col + 1] = f2tf32f(sinf(acc1[mi][ni][half*2 + 1]) * acc3[mi][ni][half*2 + 1]);
                }
            }
        }
    }
}

__global__ void aux_kernel(const float* __restrict__ probs, float* __restrict__ out, int out_size) {
    __shared__ float red[256];
    int tid = threadIdx.x;
    float s = 0.f;
    for (int idx = tid; idx < SS*EE; idx += 256) {
        int srow = idx >> 3, e = idx & 7;
        float a = 0.f;
        #pragma unroll
        for (int b = 0; b < BB; b++)
            a += probs[(size_t)((b << 10) + srow)*EE + e];
        a *= 0.25f;
        float d = (1.f / EE) - a;
        s += d * d;
    }
    red[tid] = s; __syncthreads();
    for (int o = 128; o; o >>= 1) { if (tid < o) red[tid] += red[tid + o]; __syncthreads(); }
    if (!tid && out_size > TT*DD) out[TT*DD] = red[0];
}

// ---------------- host launcher ----------------
extern "C" void kernel_launch(void* const* d_in, const int* in_sizes, int n_in,
                              void* d_out, int out_size) {
    const float* x     = (const float*)d_in[0];
    const float* c     = (const float*)d_in[1];
    const float* W_ada = (const float*)d_in[2];
    const float* b_ada = (const float*)d_in[3];
    const float* Wq    = (const float*)d_in[4];
    const float* Wk    = (const float*)d_in[5];
    const float* Wv    = (const float*)d_in[6];
    const float* Wo    = (const float*)d_in[7];
    const float* qn_w  = (const float*)d_in[8];
    const float* qn_b  = (const float*)d_in[9];
    const float* kn_w  = (const float*)d_in[10];
    const float* kn_b  = (const float*)d_in[11];
    const float* an_w  = (const float*)d_in[12];
    const float* an_b  = (const float*)d_in[13];
    const float* fn_w  = (const float*)d_in[14];
    const float* fn_b  = (const float*)d_in[15];
    const float* Wr    = (const float*)d_in[16];
    const float* br    = (const float*)d_in[17];
    const float* W1    = (const float*)d_in[18];
    const float* W2    = (const float*)d_in[19];
    const float* W3    = (const float*)d_in[20];
    float* out = (float*)d_out;

    float* buf; cudaGetSymbolAddress((void**)&buf, g_buf);
    int* ibuf;  cudaGetSymbolAddress((void**)&ibuf, g_ibuf);

    float* mods   = buf + OF_MODS;
    float* h      = buf + OF_H;
    float* q      = buf + OF_Q;
    float* k      = buf + OF_K;
    float* v      = buf + OF_V;
    float* scores = buf + OF_SC;
    float* attn   = buf + OF_AT;
    float* attnO  = buf + OF_AO;
    float* xm     = buf + OF_XM;
    float* logits = buf + OF_LG;
    float* probs  = buf + OF_PR;
    float* nrm    = buf + OF_NRM;
    float* wtl    = buf + OF_WT;
    float2* qst   = (float2*)(buf + OF_QS);
    float2* kst   = (float2*)(buf + OF_KS);
    float* G      = buf + OF_G;
    float* w1t    = buf + OF_W1T;
    float* w3t    = buf + OF_W3T;
    float* w2t    = buf + OF_W2T;
    float* wqkvt  = buf + OF_WQKVT;
    float* wot    = buf + OF_WOT;
    float* qT     = buf + OF_QT;
    float* kT     = buf + OF_KT;
    int* cnt  = ibuf + IOF_CNT;
    int* off  = ibuf + IOF_OFF;
    int* tokl = ibuf + IOF_TOK;

    cudaFuncSetAttribute(moe_up_fused_kernel, cudaFuncAttributeMaxDynamicSharedMemorySize, FUP_SMEM);

    // 0. zero out + scores + counters; weight transposes
    zero_kernel<<<(TT*DD + 255)/256, 256>>>(out, scores, cnt);
    transpose13_kernel<<<dim3(HH/32, DD/32, EE), dim3(32,8)>>>(W1, W3, w1t, w3t, DD, HH);
    transpose_kernel<true><<<dim3(DD/32, HH/32, EE), dim3(32,8)>>>(W2, w2t, HH, DD);
    transpose4_kernel<<<dim3(DD/32, DD/32, 4), dim3(32,8)>>>(Wq, Wk, Wv, Wo, wqkvt, wot);

    // 1. adaLN mods
    mods_kernel<<<dim3(BB, SIXD/256), 256>>>(c, W_ada, b_ada, mods);

    // 2. h = modulate(LN(x; an), sh_msa, sc_msa)
    ln_mod_kernel<false><<<TT/2, 256>>>(x, nullptr, h, an_w, an_b, mods, 0, DD);

    // 3. fused QKV projection — bf16 3-pass; V output pre-rounded to tf32
    b163_gemm_kernel<1,8><<<dim3(3*DD/128, TT/128), 256>>>(h, wqkvt, nullptr, DD, 3*DD, DD,
                                                           0,0,0, q, k, v);

    // 4. LN stats for q & k, then fused LN-apply + transpose to [B][D][S]
    row_stats_kernel<<<TT/2, 256>>>(q, qst);
    row_stats_kernel<<<TT/2, 256>>>(k, kst);
    transpose_ln_kernel<<<dim3(DD/32, SS/32, 2*BB), dim3(32,8)>>>(q, k, qT, kT, qst, kst,
                                                                  qn_w, qn_b, kn_w, kn_b);

    // 5. scores[b] = qT[b] @ kT[b]^T — bf16 3-pass, split-K=2 (atomicAdd, exactly
    //    2 commutative adds onto exact zero -> deterministic)
    b163_gemm_kernel<2,4><<<dim3(DD/64, DD/128, 2*BB), 256>>>(qT, kT, scores, SS/2, DD, SS,
                                                              (size_t)DD*SS, (size_t)DD*SS,
                                                              (size_t)DD*DD,
                                                              nullptr, nullptr, nullptr);

    // 6. softmax rows of 512 (shfl; output pre-rounded to tf32)
    softmax512_kernel<<<BB*DD/2, 256>>>(scores);

    // 7. attn = v @ A^T — tf32, output pre-rounded
    tf32_gemm_kernel<0,4,true><<<dim3(DD/64, SS/128, BB), 256>>>(v, scores, attn, DD, DD, DD,
                                                                 (size_t)SS*DD, (size_t)DD*DD,
                                                                 (size_t)SS*DD, 0,0,0,0);

    // 8. attnO = attn @ Wo — tf32, fp32 output
    tf32_gemm_kernel<0,4,false><<<dim3(DD/64, TT/128, 1), 256>>>(attn, wot, attnO, DD, DD, DD,
                                                                 0,0,0, 0,0,0,0);

    // 9+10. xm = modulate(LN(x + g_msa*attnO; fn), sh_mlp, sc_mlp)
    ln_mod_kernel<true><<<TT/2, 256>>>(x, attnO, xm, fn_w, fn_b, mods, 3*DD, 4*DD);

    // 11-14. routing
    logits_kernel<<<TT, 256>>>(xm, Wr, br, logits);
    nrm_kernel<<<BB*EE, 256>>>(logits, nrm);
    route_kernel<<<TT/128, 128>>>(logits, nrm, probs, cnt, tokl, wtl);
    offsets_kernel<<<1, 32>>>(cnt, off);

    // 15. fused MoE up: G = sin(xm@W1^T) * (xm@W3^T)  (G pre-rounded)
    moe_up_fused_kernel<<<dim3(HH/128, TT/128, EE), 256, FUP_SMEM>>>(xm, w1t, w3t, G,
                                                                     cnt, off, tokl);
    // 16. MoE down: out += wt * (G @ W2^T) — N64 tiles (2x blocks, better balance)
    tf32_gemm_kernel<3,4,false><<<dim3(DD/64, TT/128, EE), 256>>>(G, w2t, out, HH, DD, HH,
                                                                  0,0,0, cnt, off, tokl, wtl);

    // 17. aux loss
    aux_kernel<<<1, 256>>>(probs, out, out_size);
}

// round 14
// speedup vs baseline: 1.0304x; 1.0304x over previous
#include <cuda_runtime.h>
#include <cuda_bf16.h>
#include <math.h>
#include <stdint.h>

// Problem constants
#define BB 4
#define SS 1024
#define DD 512
#define EE 8
#define HH 1536
#define TT (BB*SS)          // 4096 tokens
#define SIXD (6*DD)         // 3072

// ---------------- scratch (device globals; no runtime allocation) ----------------
#define OF_MODS 0                            // B*6D
#define OF_H    (OF_MODS + BB*SIXD)          // T*D
#define OF_Q    (OF_H  + TT*DD)
#define OF_K    (OF_Q  + TT*DD)
#define OF_V    (OF_K  + TT*DD)
#define OF_SC   (OF_V  + TT*DD)              // B*D*D
#define OF_AT   (OF_SC + BB*DD*DD)           // T*D
#define OF_AO   (OF_AT + TT*DD)
#define OF_XM   (OF_AO + TT*DD)
#define OF_LG   (OF_XM + TT*DD)              // T*E
#define OF_PR   (OF_LG + TT*EE)              // T*E
#define OF_NRM  (OF_PR + TT*EE)              // B*E
#define OF_WT   (OF_NRM + BB*EE)             // E*T
#define OF_QS   (OF_WT + EE*TT)              // T*2 (q stats)
#define OF_KS   (OF_QS + 2*TT)               // T*2 (k stats)
#define OF_G    (OF_KS + 2*TT)               // 2T*H
#define OF_W1T  (OF_G + 2*TT*HH)             // E*H*D
#define OF_W3T  (OF_W1T + EE*HH*DD)
#define OF_W2T  (OF_W3T + EE*HH*DD)          // E*D*H
#define OF_WQKVT (OF_W2T + EE*DD*HH)         // 1536*512
#define OF_WOT  (OF_WQKVT + 3*DD*DD)         // D*D
#define OF_QT   (OF_WOT + DD*DD)             // B*D*S
#define OF_KT   (OF_QT + TT*DD)              // B*D*S
#define BUF_TOTAL (OF_KT + TT*DD)

__device__ __align__(256) float g_buf[BUF_TOTAL];

// int scratch: cnt(8) off(8) tok(E*T)
#define IOF_CNT 0
#define IOF_OFF 8
#define IOF_TOK 16
__device__ int g_ibuf[IOF_TOK + EE*TT];

// ---------------- helpers ----------------
__device__ __forceinline__ uint32_t f2tf32(float f) {
    uint32_t r;
    asm("cvt.rna.tf32.f32 %0, %1;" : "=r"(r) : "f"(f));
    return r;
}
__device__ __forceinline__ float f2tf32f(float f) {
    return __uint_as_float(f2tf32(f));
}
__device__ __forceinline__ void mma16n8k8(float* d, const uint32_t* a, const uint32_t* b) {
    asm volatile(
        "mma.sync.aligned.m16n8k8.row.col.f32.tf32.tf32.f32 "
        "{%0,%1,%2,%3}, {%4,%5,%6,%7}, {%8,%9}, {%0,%1,%2,%3};"
        : "+f"(d[0]), "+f"(d[1]), "+f"(d[2]), "+f"(d[3])
        : "r"(a[0]), "r"(a[1]), "r"(a[2]), "r"(a[3]), "r"(b[0]), "r"(b[1]));
}
__device__ __forceinline__ void mma16n8k16bf(float* d, const uint32_t* a, const uint32_t* b) {
    asm volatile(
        "mma.sync.aligned.m16n8k16.row.col.f32.bf16.bf16.f32 "
        "{%0,%1,%2,%3}, {%4,%5,%6,%7}, {%8,%9}, {%0,%1,%2,%3};"
        : "+f"(d[0]), "+f"(d[1]), "+f"(d[2]), "+f"(d[3])
        : "r"(a[0]), "r"(a[1]), "r"(a[2]), "r"(a[3]), "r"(b[0]), "r"(b[1]));
}
__device__ __forceinline__ void split2(float x, float y, uint32_t& hi, uint32_t& lo) {
    __nv_bfloat16 hx = __float2bfloat16_rn(x);
    __nv_bfloat16 hy = __float2bfloat16_rn(y);
    float rx = x - __bfloat162float(hx);
    float ry = y - __bfloat162float(hy);
    __nv_bfloat162 h2; h2.x = hx; h2.y = hy;
    __nv_bfloat162 l2; l2.x = __float2bfloat16_rn(rx); l2.y = __float2bfloat16_rn(ry);
    hi = *(uint32_t*)&h2;
    lo = *(uint32_t*)&l2;
}

// ---------------- elementwise / small kernels ----------------

__global__ void zero_kernel(float* out, int* cnt) {
    int i = blockIdx.x * 256 + threadIdx.x;
    if (i < TT*DD) out[i] = 0.f;
    if (i < EE) cnt[i] = 0;
}

__global__ void mods_kernel(const float* __restrict__ c,
                            const float* __restrict__ W_ada,
                            const float* __restrict__ b_ada,
                            float* __restrict__ mods) {
    int b   = blockIdx.x;
    int col = blockIdx.y * 256 + threadIdx.x;
    __shared__ float sc[DD];
    for (int i = threadIdx.x; i < DD; i += 256) {
        float v = c[b*DD + i];
        sc[i] = v / (1.f + expf(-v));
    }
    __syncthreads();
    float a0 = 0.f, a1 = 0.f, a2 = 0.f, a3 = 0.f;
    for (int d = 0; d < DD; d += 4) {
        a0 += sc[d+0] * W_ada[(size_t)(d+0)*SIXD + col];
        a1 += sc[d+1] * W_ada[(size_t)(d+1)*SIXD + col];
        a2 += sc[d+2] * W_ada[(size_t)(d+2)*SIXD + col];
        a3 += sc[d+3] * W_ada[(size_t)(d+3)*SIXD + col];
    }
    mods[b*SIXD + col] = b_ada[col] + ((a0 + a1) + (a2 + a3));
}

// 2 rows/block, shfl reduction.
template<bool RES>
__global__ void ln_mod_kernel(const float* __restrict__ in, const float* __restrict__ ao,
                              float* __restrict__ out,
                              const float* __restrict__ w, const float* __restrict__ bb,
                              const float* __restrict__ mods, int sh_ofs, int sc_ofs) {
    int half = threadIdx.x >> 7;
    int t    = threadIdx.x & 127;
    int row  = blockIdx.x * 2 + half;
    int bat  = row >> 10;
    const float* x = in + (size_t)row * DD;
    const float* mrow = mods + bat * SIXD;
    float v0 = x[t], v1 = x[t + 128], v2 = x[t + 256], v3 = x[t + 384];
    if (RES) {
        const float* a = ao + (size_t)row * DD;
        v0 += mrow[2*DD + t]       * a[t];
        v1 += mrow[2*DD + t + 128] * a[t + 128];
        v2 += mrow[2*DD + t + 256] * a[t + 256];
        v3 += mrow[2*DD + t + 384] * a[t + 384];
    }
    __shared__ float part[2][4];
    __shared__ float stat[2][2];
    int wsub = (threadIdx.x >> 5) & 3;
    int lane = threadIdx.x & 31;
    float s = (v0 + v1) + (v2 + v3);
    #pragma unroll
    for (int o = 16; o; o >>= 1) s += __shfl_down_sync(0xffffffffu, s, o);
    if (!lane) part[half][wsub] = s;
    __syncthreads();
    if (t == 0)
        stat[half][0] = ((part[half][0] + part[half][1]) + (part[half][2] + part[half][3])) * (1.f / DD);
    __syncthreads();
    float m = stat[half][0];
    float d0 = v0 - m, d1 = v1 - m, d2 = v2 - m, d3 = v3 - m;
    float qq = (d0*d0 + d1*d1) + (d2*d2 + d3*d3);
    #pragma unroll
    for (int o = 16; o; o >>= 1) qq += __shfl_down_sync(0xffffffffu, qq, o);
    if (!lane) part[half][wsub] = qq;
    __syncthreads();
    if (t == 0)
        stat[half][1] = rsqrtf(((part[half][0] + part[half][1]) + (part[half][2] + part[half][3])) * (1.f / DD) + 1e-5f);
    __syncthreads();
    float inv = stat[half][1];
    float* op = out + (size_t)row * DD;
    #pragma unroll
    for (int j = 0; j < 4; j++) {
        int i = t + j * 128;
        float dd = (j == 0 ? d0 : j == 1 ? d1 : j == 2 ? d2 : d3);
        float y = dd * inv * w[i] + bb[i];
        op[i] = y * (1.f + mrow[sc_ofs + i]) + mrow[sh_ofs + i];
    }
}

// per-row LN stats for BOTH q and k in one launch: blocks [0,TT/2) -> q, rest -> k.
__global__ void row_stats_qk_kernel(const float* __restrict__ qa, const float* __restrict__ ka,
                                    float2* __restrict__ qst, float2* __restrict__ kst) {
    int bi = blockIdx.x;
    const float* a;
    float2* st;
    int rowbase;
    if (bi < TT/2) { a = qa; st = qst; rowbase = bi * 2; }
    else           { a = ka; st = kst; rowbase = (bi - TT/2) * 2; }
    int half = threadIdx.x >> 7;
    int t    = threadIdx.x & 127;
    int row  = rowbase + half;
    const float* x = a + (size_t)row * DD;
    float v0 = x[t], v1 = x[t + 128], v2 = x[t + 256], v3 = x[t + 384];
    __shared__ float part[2][4];
    __shared__ float mean_s[2];
    int wsub = (threadIdx.x >> 5) & 3;
    int lane = threadIdx.x & 31;
    float s = (v0 + v1) + (v2 + v3);
    #pragma unroll
    for (int o = 16; o; o >>= 1) s += __shfl_down_sync(0xffffffffu, s, o);
    if (!lane) part[half][wsub] = s;
    __syncthreads();
    if (t == 0)
        mean_s[half] = ((part[half][0] + part[half][1]) + (part[half][2] + part[half][3])) * (1.f / DD);
    __syncthreads();
    float m = mean_s[half];
    float d0 = v0 - m, d1 = v1 - m, d2 = v2 - m, d3 = v3 - m;
    float qq = (d0*d0 + d1*d1) + (d2*d2 + d3*d3);
    #pragma unroll
    for (int o = 16; o; o >>= 1) qq += __shfl_down_sync(0xffffffffu, qq, o);
    if (!lane) part[half][wsub] = qq;
    __syncthreads();
    if (t == 0) {
        float inv = rsqrtf(((part[half][0] + part[half][1]) + (part[half][2] + part[half][3])) * (1.f / DD) + 1e-5f);
        st[row] = make_float2(m, inv);
    }
}

// fused LN-apply + transpose: dst[b][d][s] = (src[b][s][d]-m_s)*inv_s*w[d]+b[d].
__global__ void transpose_ln_kernel(const float* __restrict__ qsrc, const float* __restrict__ ksrc,
                                    float* __restrict__ qdst, float* __restrict__ kdst,
                                    const float2* __restrict__ qst, const float2* __restrict__ kst,
                                    const float* __restrict__ qw, const float* __restrict__ qb,
                                    const float* __restrict__ kw, const float* __restrict__ kb) {
    __shared__ float tbuf[32][33];
    __shared__ float2 sst[32];
    int z = blockIdx.z;
    bool isK = (z >= BB);
    int b = isK ? z - BB : z;
    const float* src = (isK ? ksrc : qsrc) + (size_t)b * SS * DD;
    float* dst       = (isK ? kdst : qdst) + (size_t)b * DD * SS;
    const float2* st = (isK ? kst : qst) + b * SS;
    const float* w   = isK ? kw : qw;
    const float* bbv = isK ? kb : qb;
    int d0 = blockIdx.x * 32;
    int s0 = blockIdx.y * 32;
    int x = threadIdx.x, y = threadIdx.y;
    if (threadIdx.y == 0) sst[x] = st[s0 + x];
    __syncthreads();
    float wv = w[d0 + x], bv = bbv[d0 + x];
    #pragma unroll
    for (int j = 0; j < 32; j += 8) {
        float v = src[(size_t)(s0 + y + j) * DD + d0 + x];
        float2 ms = sst[y + j];
        tbuf[y + j][x] = (v - ms.x) * ms.y * wv + bv;
    }
    __syncthreads();
    #pragma unroll
    for (int j = 0; j < 32; j += 8)
        dst[(size_t)(d0 + y + j) * SS + s0 + x] = tbuf[x][y + j];
}

// softmax over rows of 512; 2 rows/block, shfl; output pre-rounded to tf32
__global__ void softmax512_kernel(float* __restrict__ a) {
    int half = threadIdx.x >> 7;
    int t    = threadIdx.x & 127;
    float* row = a + (size_t)(blockIdx.x * 2 + half) * DD;
    float v0 = row[t], v1 = row[t + 128], v2 = row[t + 256], v3 = row[t + 384];
    __shared__ float part[2][4];
    __shared__ float stat[2];
    int wsub = (threadIdx.x >> 5) & 3;
    int lane = threadIdx.x & 31;
    float mx = fmaxf(fmaxf(v0, v1), fmaxf(v2, v3));
    #pragma unroll
    for (int o = 16; o; o >>= 1) mx = fmaxf(mx, __shfl_down_sync(0xffffffffu, mx, o));
    if (!lane) part[half][wsub] = mx;
    __syncthreads();
    if (t == 0)
        stat[half] = fmaxf(fmaxf(part[half][0], part[half][1]), fmaxf(part[half][2], part[half][3]));
    __syncthreads();
    float m = stat[half];
    float e0 = expf(v0 - m), e1 = expf(v1 - m), e2 = expf(v2 - m), e3 = expf(v3 - m);
    float s = (e0 + e1) + (e2 + e3);
    #pragma unroll
    for (int o = 16; o; o >>= 1) s += __shfl_down_sync(0xffffffffu, s, o);
    if (!lane) part[half][wsub] = s;
    __syncthreads();
    if (t == 0)
        stat[half] = 1.f / ((part[half][0] + part[half][1]) + (part[half][2] + part[half][3]));
    __syncthreads();
    float inv = stat[half];
    row[t]       = f2tf32f(e0 * inv);
    row[t + 128] = f2tf32f(e1 * inv);
    row[t + 256] = f2tf32f(e2 * inv);
    row[t + 384] = f2tf32f(e3 * inv);
}

__global__ void logits_kernel(const float* __restrict__ xm, const float* __restrict__ Wr,
                              const float* __restrict__ br, float* __restrict__ logits) {
    int t = blockIdx.x;
    __shared__ float s[DD];
    for (int i = threadIdx.x; i < DD; i += 256) s[i] = xm[(size_t)t*DD + i];
    __syncthreads();
    int w = threadIdx.x >> 5, lane = threadIdx.x & 31;
    float acc = 0.f;
    for (int d = lane; d < DD; d += 32) acc += s[d] * Wr[d*EE + w];
    for (int o = 16; o; o >>= 1) acc += __shfl_down_sync(0xffffffffu, acc, o);
    if (!lane) logits[t*EE + w] = acc + br[w];
}

__global__ void nrm_kernel(const float* __restrict__ logits, float* __restrict__ nrm) {
    int be = blockIdx.x, b = be >> 3, e = be & 7;
    int tid = threadIdx.x;
    float s = 0.f;
    for (int si = tid; si < SS; si += 256) {
        float v = logits[(size_t)((b << 10) + si)*EE + e];
        s += v * v;
    }
    __shared__ float red[256];
    red[tid] = s; __syncthreads();
    for (int o = 128; o; o >>= 1) { if (tid < o) red[tid] += red[tid + o]; __syncthreads(); }
    if (!tid) nrm[be] = sqrtf(red[0]);
}

__global__ void route_kernel(const float* __restrict__ logits, const float* __restrict__ nrm,
                             float* __restrict__ probs, int* __restrict__ cnt,
                             int* __restrict__ tokl, float* __restrict__ wtl) {
    int t = blockIdx.x * 128 + threadIdx.x;
    if (t >= TT) return;
    int b = t >> 10;
    float l[EE];
    float mx = -1e30f;
    #pragma unroll
    for (int e = 0; e < EE; e++) {
        l[e] = logits[t*EE + e] / fmaxf(nrm[b*EE + e], 1e-12f);
        mx = fmaxf(mx, l[e]);
    }
    float sum = 0.f;
    #pragma unroll
    for (int e = 0; e < EE; e++) { l[e] = expf(l[e] - mx); sum += l[e]; }
    float inv = 1.f / sum;
    #pragma unroll
    for (int e = 0; e < EE; e++) { l[e] *= inv; probs[t*EE + e] = l[e]; }
    int i0 = 0;
    #pragma unroll
    for (int e = 1; e < EE; e++) if (l[e] > l[i0]) i0 = e;
    int i1 = -1;
    #pragma unroll
    for (int e = 0; e < EE; e++) {
        if (e == i0) continue;
        if (i1 < 0 || l[e] > l[i1]) i1 = e;
    }
    int p0 = atomicAdd(&cnt[i0], 1);
    tokl[i0*TT + p0] = t; wtl[i0*TT + p0] = l[i0];
    int p1 = atomicAdd(&cnt[i1], 1);
    tokl[i1*TT + p1] = t; wtl[i1*TT + p1] = l[i1];
}

__global__ void offsets_kernel(const int* __restrict__ cnt, int* __restrict__ off) {
    if (threadIdx.x == 0) {
        int a = 0;
        for (int e = 0; e < EE; e++) { off[e] = a; a += cnt[e]; }
    }
}

// 32x32 tiled transpose, per z-slice.  RND: pre-round to tf32.
template<bool RND>
__global__ void transpose_kernel(const float* __restrict__ src, float* __restrict__ dst,
                                 int R, int C) {
    __shared__ float t[32][33];
    size_t eb = (size_t)blockIdx.z * R * C;
    int c0 = blockIdx.x * 32, r0 = blockIdx.y * 32;
    int x = threadIdx.x, y = threadIdx.y;
    #pragma unroll
    for (int j = 0; j < 32; j += 8) {
        float v = src[eb + (size_t)(r0 + y + j) * C + c0 + x];
        t[y + j][x] = RND ? f2tf32f(v) : v;
    }
    __syncthreads();
    #pragma unroll
    for (int j = 0; j < 32; j += 8)
        dst[eb + (size_t)(c0 + y + j) * R + r0 + x] = t[x][y + j];
}

// merged 4x DxD transpose: z=0..3 -> Wq,Wk,Wv (no round) | Wo (rounded)
__global__ void transpose4_kernel(const float* __restrict__ Wq, const float* __restrict__ Wk,
                                  const float* __restrict__ Wv, const float* __restrict__ Wo,
                                  float* __restrict__ wqkvt, float* __restrict__ wot) {
    __shared__ float t[32][33];
    int z = blockIdx.z;
    const float* src = (z == 0) ? Wq : (z == 1) ? Wk : (z == 2) ? Wv : Wo;
    float* dst = (z == 3) ? wot : (wqkvt + (size_t)z * DD * DD);
    bool rnd = (z == 3);
    int c0 = blockIdx.x * 32, r0 = blockIdx.y * 32;
    int x = threadIdx.x, y = threadIdx.y;
    #pragma unroll
    for (int j = 0; j < 32; j += 8) {
        float v = src[(size_t)(r0 + y + j) * DD + c0 + x];
        t[y + j][x] = rnd ? f2tf32f(v) : v;
    }
    __syncthreads();
    #pragma unroll
    for (int j = 0; j < 32; j += 8)
        dst[(size_t)(c0 + y + j) * DD + r0 + x] = t[x][y + j];
}

// dual transpose: W1 & W3 in one pass, pre-rounded to tf32
__global__ void transpose13_kernel(const float* __restrict__ s1, const float* __restrict__ s3,
                                   float* __restrict__ d1, float* __restrict__ d3,
                                   int R, int C) {
    __shared__ float t1[32][33];
    __shared__ float t3[32][33];
    size_t eb = (size_t)blockIdx.z * R * C;
    int c0 = blockIdx.x * 32, r0 = blockIdx.y * 32;
    int x = threadIdx.x, y = threadIdx.y;
    #pragma unroll
    for (int j = 0; j < 32; j += 8) {
        size_t si = eb + (size_t)(r0 + y + j) * C + c0 + x;
        t1[y + j][x] = f2tf32f(s1[si]);
        t3[y + j][x] = f2tf32f(s3[si]);
    }
    __syncthreads();
    #pragma unroll
    for (int j = 0; j < 32; j += 8) {
        size_t di = eb + (size_t)(c0 + y + j) * R + r0 + x;
        d1[di] = t1[x][y + j];
        d3[di] = t3[x][y + j];
    }
}

// ============ bf16 3-pass "fp32-equivalent" GEMM: C = A @ Bt^T ============
// MODE 0: dense batched (strides).  MODE 1: QKV split write (V pre-rounded to tf32).
template<int MODE, int NI>
__global__ void __launch_bounds__(256, 2)
b163_gemm_kernel(const float* __restrict__ A, const float* __restrict__ Bt,
                 float* __restrict__ C, int K, int N,
                 size_t sA, size_t sB, size_t sC,
                 float* __restrict__ Qo, float* __restrict__ Ko, float* __restrict__ Vo) {
    constexpr int NT = NI * 16;
    __shared__ uint32_t Ah[128][12], Al[128][12];
    __shared__ uint32_t Bh[NT][12],  Bl[NT][12];

    const int tid = threadIdx.x;
    const int n0 = blockIdx.x * NT;
    const int m0 = blockIdx.y * 128;
    if (MODE == 0) {
        A += blockIdx.z * sA; Bt += blockIdx.z * sB; C += blockIdx.z * sC;
    }

    const int wid = tid >> 5, lid = tid & 31;
    const int w_m = (wid & 3) * 32, w_n = (wid >> 2) * (NI * 8);
    const int lq = lid >> 2, lr = lid & 3;
    const int rowA = tid >> 1, cA = (tid & 1) * 8;
    const int rowB = (NI == 8) ? (tid >> 1) : (tid >> 2);
    const int cB   = (NI == 8) ? ((tid & 1) * 8) : ((tid & 3) * 4);

    float acc[2][NI][4];
    #pragma unroll
    for (int i = 0; i < 2; i++)
        #pragma unroll
        for (int j = 0; j < NI; j++)
            #pragma unroll
            for (int l = 0; l < 4; l++) acc[i][j][l] = 0.f;

    float4 ra0, ra1, rb0, rb1;
    auto LDG = [&](int t) {
        const float* ap = A + (size_t)(m0 + rowA) * K + t*16 + cA;
        ra0 = *(const float4*)ap; ra1 = *(const float4*)(ap + 4);
        const float* bp = Bt + (size_t)(n0 + rowB) * K + t*16 + cB;
        rb0 = *(const float4*)bp;
        if (NI == 8) rb1 = *(const float4*)(bp + 4);
    };

    const int NK = K / 16;
    LDG(0);
    for (int i = 0; i < NK; i++) {
        {
            uint32_t* aph = &Ah[rowA][cA/2];
            uint32_t* apl = &Al[rowA][cA/2];
            split2(ra0.x, ra0.y, aph[0], apl[0]);
            split2(ra0.z, ra0.w, aph[1], apl[1]);
            split2(ra1.x, ra1.y, aph[2], apl[2]);
            split2(ra1.z, ra1.w, aph[3], apl[3]);
            uint32_t* bph = &Bh[rowB][cB/2];
            uint32_t* bpl = &Bl[rowB][cB/2];
            split2(rb0.x, rb0.y, bph[0], bpl[0]);
            split2(rb0.z, rb0.w, bph[1], bpl[1]);
            if (NI == 8) {
                split2(rb1.x, rb1.y, bph[2], bpl[2]);
                split2(rb1.z, rb1.w, bph[3], bpl[3]);
            }
        }
        __syncthreads();
        if (i + 1 < NK) LDG(i + 1);
        uint32_t ah[2][4], al[2][4];
        #pragma unroll
        for (int mi = 0; mi < 2; mi++) {
            int mr = w_m + mi*16 + lq;
            ah[mi][0] = Ah[mr    ][lr];     al[mi][0] = Al[mr    ][lr];
            ah[mi][1] = Ah[mr + 8][lr];     al[mi][1] = Al[mr + 8][lr];
            ah[mi][2] = Ah[mr    ][4 + lr]; al[mi][2] = Al[mr    ][4 + lr];
            ah[mi][3] = Ah[mr + 8][4 + lr]; al[mi][3] = Al[mr + 8][4 + lr];
        }
        #pragma unroll
        for (int ni = 0; ni < NI; ni++) {
            int nr = w_n + ni*8 + lq;
            uint32_t bh[2], bl[2];
            bh[0] = Bh[nr][lr]; bh[1] = Bh[nr][4 + lr];
            bl[0] = Bl[nr][lr]; bl[1] = Bl[nr][4 + lr];
            mma16n8k16bf(acc[0][ni], ah[0], bh);
            mma16n8k16bf(acc[1][ni], ah[1], bh);
            mma16n8k16bf(acc[0][ni], ah[0], bl);
            mma16n8k16bf(acc[1][ni], ah[1], bl);
            mma16n8k16bf(acc[0][ni], al[0], bh);
            mma16n8k16bf(acc[1][ni], al[1], bh);
        }
        __syncthreads();
    }

    float* base = C;
    int csub = 0;
    bool isV = false;
    if (MODE == 1) {
        if (n0 < 512)       { base = Qo; csub = 0; }
        else if (n0 < 1024) { base = Ko; csub = 512; }
        else                { base = Vo; csub = 1024; isV = true; }
    }
    #pragma unroll
    for (int mi = 0; mi < 2; mi++) {
        #pragma unroll
        for (int half = 0; half < 2; half++) {
            int r = w_m + mi*16 + lq + half*8;
            #pragma unroll
            for (int ni = 0; ni < NI; ni++) {
                float v0 = acc[mi][ni][half*2 + 0];
                float v1 = acc[mi][ni][half*2 + 1];
                int col = w_n + ni*8 + 2*lr;
                if (MODE == 0) {
                    float* cp = C + (size_t)(m0 + r) * N + n0 + col;
                    cp[0] = v0; cp[1] = v1;
                } else {
                    float* cp = base + (size_t)(m0 + r) * DD + (n0 - csub) + col;
                    if (isV) { cp[0] = f2tf32f(v0); cp[1] = f2tf32f(v1); }
                    else     { cp[0] = v0;          cp[1] = v1; }
                }
            }
        }
    }
}

// ============ tf32 mma.sync GEMM: pre-rounded inputs, raw bit copy ============
template<int MODE, int NI, bool CVTOUT>
__global__ void __launch_bounds__(256, 2)
tf32_gemm_kernel(const float* __restrict__ A, const float* __restrict__ Bt,
                 float* __restrict__ C, int K, int N, int ldA,
                 size_t sA, size_t sB, size_t sC,
                 const int* __restrict__ cnt, const int* __restrict__ off,
                 const int* __restrict__ tokl, const float* __restrict__ wtl) {
    constexpr int NT = NI * 16;
    __shared__ uint32_t As[128][36];
    __shared__ uint32_t Bs[NT][36];
    __shared__ int stok[128];
    __shared__ float swt[128];

    const int tid = threadIdx.x;
    const int n0 = blockIdx.x * NT;
    int m0 = 0, count = 0, t0 = 0, gbase = 0;

    if (MODE == 0) {
        m0 = blockIdx.y * 128;
        A += blockIdx.z * sA; Bt += blockIdx.z * sB; C += blockIdx.z * sC;
    } else {
        const int e = blockIdx.z;
        count = cnt[e];
        t0 = blockIdx.y * 128;
        if (t0 >= count) return;
        gbase = off[e] + t0;
        if (tid < 128) {
            bool ok = (t0 + tid) < count;
            stok[tid] = ok ? tokl[e*TT + t0 + tid] : -1;
            swt[tid]  = ok ? wtl [e*TT + t0 + tid] : 0.f;
        }
        Bt += (size_t)e * N * K;
        __syncthreads();
    }

    const int wid = tid >> 5, lid = tid & 31;
    const int w_m = (wid & 3) * 32, w_n = (wid >> 2) * (NI * 8);
    const int lq = lid >> 2, lr = lid & 3;
    const int row_l = tid >> 3, c4 = tid & 7;

    float acc[2][NI][4];
    #pragma unroll
    for (int i = 0; i < 2; i++)
        #pragma unroll
        for (int j = 0; j < NI; j++)
            #pragma unroll
            for (int l = 0; l < 4; l++) acc[i][j][l] = 0.f;

    float4 ra[4], rb[NI/2];
    auto LDG = [&](int t) {
        #pragma unroll
        for (int j = 0; j < 4; j++) {
            int row = row_l + j * 32;
            if (MODE == 0) {
                ra[j] = *(const float4*)(A + (size_t)(m0 + row) * ldA + t*32 + c4*4);
            } else {
                ra[j] = make_float4(0.f,0.f,0.f,0.f);
                if (t0 + row < count)
                    ra[j] = *(const float4*)(A + (size_t)(gbase + row) * K + t*32 + c4*4);
            }
        }
        #pragma unroll
        for (int j = 0; j < NI/2; j++) {
            int row = row_l + j * 32;
            rb[j] = *(const float4*)(Bt + (size_t)(n0 + row) * K + t*32 + c4*4);
        }
    };

    const int NK = K / 32;
    LDG(0);
    for (int i = 0; i < NK; i++) {
        #pragma unroll
        for (int j = 0; j < 4; j++) {
            int row = row_l + j * 32;
            uint32_t* ap = &As[row][c4*4];
            ap[0] = __float_as_uint(ra[j].x); ap[1] = __float_as_uint(ra[j].y);
            ap[2] = __float_as_uint(ra[j].z); ap[3] = __float_as_uint(ra[j].w);
        }
        #pragma unroll
        for (int j = 0; j < NI/2; j++) {
            int row = row_l + j * 32;
            uint32_t* bp = &Bs[row][c4*4];
            bp[0] = __float_as_uint(rb[j].x); bp[1] = __float_as_uint(rb[j].y);
            bp[2] = __float_as_uint(rb[j].z); bp[3] = __float_as_uint(rb[j].w);
        }
        __syncthreads();
        if (i + 1 < NK) LDG(i + 1);
        #pragma unroll
        for (int ks = 0; ks < 32; ks += 8) {
            uint32_t af[2][4], bf[NI][2];
            #pragma unroll
            for (int mi = 0; mi < 2; mi++) {
                int mr = w_m + mi*16 + lq;
                af[mi][0] = As[mr    ][ks + lr];
                af[mi][1] = As[mr + 8][ks + lr];
                af[mi][2] = As[mr    ][ks + 4 + lr];
                af[mi][3] = As[mr + 8][ks + 4 + lr];
            }
            #pragma unroll
            for (int ni = 0; ni < NI; ni++) {
                int nr = w_n + ni*8 + lq;
                bf[ni][0] = Bs[nr][ks + lr];
                bf[ni][1] = Bs[nr][ks + 4 + lr];
            }
            #pragma unroll
            for (int mi = 0; mi < 2; mi++)
                #pragma unroll
                for (int ni = 0; ni < NI; ni++)
                    mma16n8k8(acc[mi][ni], af[mi], bf[ni]);
        }
        __syncthreads();
    }

    #pragma unroll
    for (int mi = 0; mi < 2; mi++) {
        #pragma unroll
        for (int half = 0; half < 2; half++) {
            int r = w_m + mi*16 + lq + half*8;
            #pragma unroll
            for (int ni = 0; ni < NI; ni++) {
                float v0 = acc[mi][ni][half*2 + 0];
                float v1 = acc[mi][ni][half*2 + 1];
                int col = w_n + ni*8 + 2*lr;
                if (MODE == 0) {
                    float* cp = C + (size_t)(m0 + r) * N + n0 + col;
                    if (CVTOUT) { cp[0] = f2tf32f(v0); cp[1] = f2tf32f(v1); }
                    else        { cp[0] = v0;          cp[1] = v1; }
                } else {
                    if (t0 + r < count) {
                        int tk = stok[r];
                        float wt = swt[r];
                        float* op = C + (size_t)tk * DD + n0 + col;
                        atomicAdd(op + 0, wt * v0);
                        atomicAdd(op + 1, wt * v1);
                    }
                }
            }
        }
    }
}

// ============ fused MoE up: G = sin(xm@W1t^T) * (xm@W3t^T) ============
#define FUP_SMEM (3 * 128 * 36 * 4)
__global__ void __launch_bounds__(256)
moe_up_fused_kernel(const float* __restrict__ xm,
                    const float* __restrict__ B1t, const float* __restrict__ B3t,
                    float* __restrict__ G,
                    const int* __restrict__ cnt, const int* __restrict__ off,
                    const int* __restrict__ tokl) {
    extern __shared__ uint32_t dsm[];
    typedef uint32_t Row[36];
    Row* As  = (Row*)(dsm);
    Row* B1s = (Row*)(dsm + 128*36);
    Row* B3s = (Row*)(dsm + 2*128*36);
    __shared__ int stok[128];

    const int tid = threadIdx.x;
    const int e = blockIdx.z;
    const int count = cnt[e];
    const int t0 = blockIdx.y * 128;
    if (t0 >= count) return;
    const int n0 = blockIdx.x * 128;
    const int gbase = off[e] + t0;
    if (tid < 128)
        stok[tid] = (t0 + tid < count) ? tokl[e*TT + t0 + tid] : -1;
    B1t += (size_t)e * HH * DD;
    B3t += (size_t)e * HH * DD;
    __syncthreads();

    const int wid = tid >> 5, lid = tid & 31;
    const int w_m = (wid & 3) * 32, w_n = (wid >> 2) * 64;
    const int lq = lid >> 2, lr = lid & 3;
    const int row_l = tid >> 3, c4 = tid & 7;

    float acc1[2][8][4], acc3[2][8][4];
    #pragma unroll
    for (int i = 0; i < 2; i++)
        #pragma unroll
        for (int j = 0; j < 8; j++)
            #pragma unroll
            for (int l = 0; l < 4; l++) { acc1[i][j][l] = 0.f; acc3[i][j][l] = 0.f; }

    float4 ra[4], rb1[4], rb3[4];
    auto LDG = [&](int t) {
        #pragma unroll
        for (int j = 0; j < 4; j++) {
            int row = row_l + j * 32;
            int tk = stok[row];
            ra[j] = make_float4(0.f,0.f,0.f,0.f);
            if (tk >= 0)
                ra[j] = *(const float4*)(xm + (size_t)tk * DD + t*32 + c4*4);
            rb1[j] = *(const float4*)(B1t + (size_t)(n0 + row) * DD + t*32 + c4*4);
            rb3[j] = *(const float4*)(B3t + (size_t)(n0 + row) * DD + t*32 + c4*4);
        }
    };

    const int NK = DD / 32;
    LDG(0);
    for (int i = 0; i < NK; i++) {
        #pragma unroll
        for (int j = 0; j < 4; j++) {
            int row = row_l + j * 32;
            uint32_t* ap  = &As[row][c4*4];
            uint32_t* b1p = &B1s[row][c4*4];
            uint32_t* b3p = &B3s[row][c4*4];
            ap[0]  = f2tf32(ra[j].x);  ap[1]  = f2tf32(ra[j].y);
            ap[2]  = f2tf32(ra[j].z);  ap[3]  = f2tf32(ra[j].w);
            b1p[0] = __float_as_uint(rb1[j].x); b1p[1] = __float_as_uint(rb1[j].y);
            b1p[2] = __float_as_uint(rb1[j].z); b1p[3] = __float_as_uint(rb1[j].w);
            b3p[0] = __float_as_uint(rb3[j].x); b3p[1] = __float_as_uint(rb3[j].y);
            b3p[2] = __float_as_uint(rb3[j].z); b3p[3] = __float_as_uint(rb3[j].w);
        }
        __syncthreads();
        if (i + 1 < NK) LDG(i + 1);
        #pragma unroll
        for (int ks = 0; ks < 32; ks += 8) {
            uint32_t af[2][4];
            #pragma unroll
            for (int mi = 0; mi < 2; mi++) {
                int mr = w_m + mi*16 + lq;
                af[mi][0] = As[mr    ][ks + lr];
                af[mi][1] = As[mr + 8][ks + lr];
                af[mi][2] = As[mr    ][ks + 4 + lr];
                af[mi][3] = As[mr + 8][ks + 4 + lr];
            }
            #pragma unroll
            for (int ni = 0; ni < 8; ni++) {
                int nr = w_n + ni*8 + lq;
                uint32_t b1[2], b3[2];
                b1[0] = B1s[nr][ks + lr]; b1[1] = B1s[nr][ks + 4 + lr];
                b3[0] = B3s[nr][ks + lr]; b3[1] = B3s[nr][ks + 4 + lr];
                mma16n8k8(acc1[0][ni], af[0], b1);
                mma16n8k8(acc1[1][ni], af[1], b1);
                mma16n8k8(acc3[0][ni], af[0], b3);
                mma16n8k8(acc3[1][ni], af[1], b3);
            }
        }
        __syncthreads();
    }

    #pragma unroll
    for (int mi = 0; mi < 2; mi++) {
        #pragma unroll
        for (int half = 0; half < 2; half++) {
            int r = w_m + mi*16 + lq + half*8;
            if (t0 + r < count) {
                float* gp = G + (size_t)(gbase + r) * HH + n0;
                #pragma unroll
                for (int ni = 0; ni < 8; ni++) {
                    int col = w_n + ni*8 + 2*lr;
                    gp[col + 0] = f2tf32f(sinf(acc1[mi][ni][half*2 + 0]) * acc3[mi][ni][half*2 + 0]);
                    gp[col + 1] = f2tf32f(sinf(acc1[mi][ni][half*2 + 1]) * acc3[mi][ni][half*2 + 1]);
                }
            }
        }
    }
}

__global__ void aux_kernel(const float* __restrict__ probs, float* __restrict__ out, int out_size) {
    __shared__ float red[256];
    int tid = threadIdx.x;
    float s = 0.f;
    for (int idx = tid; idx < SS*EE; idx += 256) {
        int srow = idx >> 3, e = idx & 7;
        float a = 0.f;
        #pragma unroll
        for (int b = 0; b < BB; b++)
            a += probs[(size_t)((b << 10) + srow)*EE + e];
        a *= 0.25f;
        float d = (1.f / EE) - a;
        s += d * d;
    }
    red[tid] = s; __syncthreads();
    for (int o = 128; o; o >>= 1) { if (tid < o) red[tid] += red[tid + o]; __syncthreads(); }
    if (!tid && out_size > TT*DD) out[TT*DD] = red[0];
}

// ---------------- host launcher ----------------
extern "C" void kernel_launch(void* const* d_in, const int* in_sizes, int n_in,
                              void* d_out, int out_size) {
    const float* x     = (const float*)d_in[0];
    const float* c     = (const float*)d_in[1];
    const float* W_ada = (const float*)d_in[2];
    const float* b_ada = (const float*)d_in[3];
    const float* Wq    = (const float*)d_in[4];
    const float* Wk    = (const float*)d_in[5];
    const float* Wv    = (const float*)d_in[6];
    const float* Wo    = (const float*)d_in[7];
    const float* qn_w  = (const float*)d_in[8];
    const float* qn_b  = (const float*)d_in[9];
    const float* kn_w  = (const float*)d_in[10];
    const float* kn_b  = (const float*)d_in[11];
    const float* an_w  = (const float*)d_in[12];
    const float* an_b  = (const float*)d_in[13];
    const float* fn_w  = (const float*)d_in[14];
    const float* fn_b  = (const float*)d_in[15];
    const float* Wr    = (const float*)d_in[16];
    const float* br    = (const float*)d_in[17];
    const float* W1    = (const float*)d_in[18];
    const float* W2    = (const float*)d_in[19];
    const float* W3    = (const float*)d_in[20];
    float* out = (float*)d_out;

    float* buf; cudaGetSymbolAddress((void**)&buf, g_buf);
    int* ibuf;  cudaGetSymbolAddress((void**)&ibuf, g_ibuf);

    float* mods   = buf + OF_MODS;
    float* h      = buf + OF_H;
    float* q      = buf + OF_Q;
    float* k      = buf + OF_K;
    float* v      = buf + OF_V;
    float* scores = buf + OF_SC;
    float* attn   = buf + OF_AT;
    float* attnO  = buf + OF_AO;
    float* xm     = buf + OF_XM;
    float* logits = buf + OF_LG;
    float* probs  = buf + OF_PR;
    float* nrm    = buf + OF_NRM;
    float* wtl    = buf + OF_WT;
    float2* qst   = (float2*)(buf + OF_QS);
    float2* kst   = (float2*)(buf + OF_KS);
    float* G      = buf + OF_G;
    float* w1t    = buf + OF_W1T;
    float* w3t    = buf + OF_W3T;
    float* w2t    = buf + OF_W2T;
    float* wqkvt  = buf + OF_WQKVT;
    float* wot    = buf + OF_WOT;
    float* qT     = buf + OF_QT;
    float* kT     = buf + OF_KT;
    int* cnt  = ibuf + IOF_CNT;
    int* off  = ibuf + IOF_OFF;
    int* tokl = ibuf + IOF_TOK;

    cudaFuncSetAttribute(moe_up_fused_kernel, cudaFuncAttributeMaxDynamicSharedMemorySize, FUP_SMEM);

    // 0. zero out + counters; weight transposes (pre-rounded where tf32-exclusive)
    zero_kernel<<<(TT*DD + 255)/256, 256>>>(out, cnt);
    transpose13_kernel<<<dim3(HH/32, DD/32, EE), dim3(32,8)>>>(W1, W3, w1t, w3t, DD, HH);
    transpose_kernel<true><<<dim3(DD/32, HH/32, EE), dim3(32,8)>>>(W2, w2t, HH, DD);
    transpose4_kernel<<<dim3(DD/32, DD/32, 4), dim3(32,8)>>>(Wq, Wk, Wv, Wo, wqkvt, wot);

    // 1. adaLN mods
    mods_kernel<<<dim3(BB, SIXD/256), 256>>>(c, W_ada, b_ada, mods);

    // 2. h = modulate(LN(x; an), sh_msa, sc_msa)
    ln_mod_kernel<false><<<TT/2, 256>>>(x, nullptr, h, an_w, an_b, mods, 0, DD);

    // 3. fused QKV projection — bf16 3-pass; V output pre-rounded to tf32
    b163_gemm_kernel<1,8><<<dim3(3*DD/128, TT/128), 256>>>(h, wqkvt, nullptr, DD, 3*DD,
                                                           0,0,0, q, k, v);

    // 4. LN stats for q & k (single launch), then fused LN-apply + transpose
    row_stats_qk_kernel<<<TT, 256>>>(q, k, qst, kst);
    transpose_ln_kernel<<<dim3(DD/32, SS/32, 2*BB), dim3(32,8)>>>(q, k, qT, kT, qst, kst,
                                                                  qn_w, qn_b, kn_w, kn_b);

    // 5. scores[b] = qT[b] @ kT[b]^T — bf16 3-pass, N64 tiles
    b163_gemm_kernel<0,4><<<dim3(DD/64, DD/128, BB), 256>>>(qT, kT, scores, SS, DD,
                                                            (size_t)DD*SS, (size_t)DD*SS,
                                                            (size_t)DD*DD,
                                                            nullptr, nullptr, nullptr);

    // 6. softmax rows of 512 (shfl; output pre-rounded to tf32)
    softmax512_kernel<<<BB*DD/2, 256>>>(scores);

    // 7. attn = v @ A^T — tf32, output pre-rounded
    tf32_gemm_kernel<0,4,true><<<dim3(DD/64, SS/128, BB), 256>>>(v, scores, attn, DD, DD, DD,
                                                                 (size_t)SS*DD, (size_t)DD*DD,
                                                                 (size_t)SS*DD, 0,0,0,0);

    // 8. attnO = attn @ Wo — tf32, fp32 output
    tf32_gemm_kernel<0,4,false><<<dim3(DD/64, TT/128, 1), 256>>>(attn, wot, attnO, DD, DD, DD,
                                                                 0,0,0, 0,0,0,0);

    // 9+10. xm = modulate(LN(x + g_msa*attnO; fn), sh_mlp, sc_mlp)
    ln_mod_kernel<true><<<TT/2, 256>>>(x, attnO, xm, fn_w, fn_b, mods, 3*DD, 4*DD);

    // 11-14. routing
    logits_kernel<<<TT, 256>>>(xm, Wr, br, logits);
    nrm_kernel<<<BB*EE, 256>>>(logits, nrm);
    route_kernel<<<TT/128, 128>>>(logits, nrm, probs, cnt, tokl, wtl);
    offsets_kernel<<<1, 32>>>(cnt, off);

    // 15. fused MoE up: G = sin(xm@W1^T) * (xm@W3^T)  (G pre-rounded)
    moe_up_fused_kernel<<<dim3(HH/128, TT/128, EE), 256, FUP_SMEM>>>(xm, w1t, w3t, G,
                                                                     cnt, off, tokl);
    // 16. MoE down: out += wt * (G @ W2^T)
    tf32_gemm_kernel<3,8,false><<<dim3(DD/128, TT/128, EE), 256>>>(G, w2t, out, HH, DD, HH,
                                                                   0,0,0, cnt, off, tokl, wtl);

    // 17. aux loss
    aux_kernel<<<1, 256>>>(probs, out, out_size);
}

// round 15
// speedup vs baseline: 1.0604x; 1.0292x over previous
#include <cuda_runtime.h>
#include <cuda_bf16.h>
#include <math.h>
#include <stdint.h>

// Problem constants
#define BB 4
#define SS 1024
#define DD 512
#define EE 8
#define HH 1536
#define TT (BB*SS)          // 4096 tokens
#define SIXD (6*DD)         // 3072

// ---------------- scratch (device globals; no runtime allocation) ----------------
#define OF_MODS 0                            // B*6D
#define OF_H    (OF_MODS + BB*SIXD)          // T*D
#define OF_Q    (OF_H  + TT*DD)
#define OF_K    (OF_Q  + TT*DD)
#define OF_V    (OF_K  + TT*DD)
#define OF_SC   (OF_V  + TT*DD)              // B*D*D
#define OF_AT   (OF_SC + BB*DD*DD)           // T*D
#define OF_AO   (OF_AT + TT*DD)
#define OF_XM   (OF_AO + TT*DD)
#define OF_LG   (OF_XM + TT*DD)              // T*E
#define OF_PR   (OF_LG + TT*EE)              // T*E
#define OF_NRM  (OF_PR + TT*EE)              // B*E
#define OF_WT   (OF_NRM + BB*EE)             // E*T
#define OF_QS   (OF_WT + EE*TT)              // T*2 (q stats)
#define OF_KS   (OF_QS + 2*TT)               // T*2 (k stats)
#define OF_G    (OF_KS + 2*TT)               // 2T*H
#define OF_W1T  (OF_G + 2*TT*HH)             // E*H*D
#define OF_W3T  (OF_W1T + EE*HH*DD)
#define OF_W2T  (OF_W3T + EE*HH*DD)          // E*D*H
#define OF_WQKVT (OF_W2T + EE*DD*HH)         // 1536*512
#define OF_WOT  (OF_WQKVT + 3*DD*DD)         // D*D
#define OF_QT   (OF_WOT + DD*DD)             // B*D*S
#define OF_KT   (OF_QT + TT*DD)              // B*D*S
#define BUF_TOTAL (OF_KT + TT*DD)

__device__ __align__(256) float g_buf[BUF_TOTAL];

// int scratch: cnt(8) off(8) tok(E*T)
#define IOF_CNT 0
#define IOF_OFF 8
#define IOF_TOK 16
__device__ int g_ibuf[IOF_TOK + EE*TT];

// ---------------- helpers ----------------
__device__ __forceinline__ uint32_t f2tf32(float f) {
    uint32_t r;
    asm("cvt.rna.tf32.f32 %0, %1;" : "=r"(r) : "f"(f));
    return r;
}
__device__ __forceinline__ float f2tf32f(float f) {
    return __uint_as_float(f2tf32(f));
}
__device__ __forceinline__ void mma16n8k8(float* d, const uint32_t* a, const uint32_t* b) {
    asm volatile(
        "mma.sync.aligned.m16n8k8.row.col.f32.tf32.tf32.f32 "
        "{%0,%1,%2,%3}, {%4,%5,%6,%7}, {%8,%9}, {%0,%1,%2,%3};"
        : "+f"(d[0]), "+f"(d[1]), "+f"(d[2]), "+f"(d[3])
        : "r"(a[0]), "r"(a[1]), "r"(a[2]), "r"(a[3]), "r"(b[0]), "r"(b[1]));
}
__device__ __forceinline__ void mma16n8k16bf(float* d, const uint32_t* a, const uint32_t* b) {
    asm volatile(
        "mma.sync.aligned.m16n8k16.row.col.f32.bf16.bf16.f32 "
        "{%0,%1,%2,%3}, {%4,%5,%6,%7}, {%8,%9}, {%0,%1,%2,%3};"
        : "+f"(d[0]), "+f"(d[1]), "+f"(d[2]), "+f"(d[3])
        : "r"(a[0]), "r"(a[1]), "r"(a[2]), "r"(a[3]), "r"(b[0]), "r"(b[1]));
}
__device__ __forceinline__ void split2(float x, float y, uint32_t& hi, uint32_t& lo) {
    __nv_bfloat16 hx = __float2bfloat16_rn(x);
    __nv_bfloat16 hy = __float2bfloat16_rn(y);
    float rx = x - __bfloat162float(hx);
    float ry = y - __bfloat162float(hy);
    __nv_bfloat162 h2; h2.x = hx; h2.y = hy;
    __nv_bfloat162 l2; l2.x = __float2bfloat16_rn(rx); l2.y = __float2bfloat16_rn(ry);
    hi = *(uint32_t*)&h2;
    lo = *(uint32_t*)&l2;
}

// ---------------- elementwise / small kernels ----------------

__global__ void zero_kernel(float* out, int* cnt) {
    int i = blockIdx.x * 256 + threadIdx.x;
    if (i < TT*DD) out[i] = 0.f;
    if (i < EE) cnt[i] = 0;
}

__global__ void mods_kernel(const float* __restrict__ c,
                            const float* __restrict__ W_ada,
                            const float* __restrict__ b_ada,
                            float* __restrict__ mods) {
    int b   = blockIdx.x;
    int col = blockIdx.y * 256 + threadIdx.x;
    __shared__ float sc[DD];
    for (int i = threadIdx.x; i < DD; i += 256) {
        float v = c[b*DD + i];
        sc[i] = v / (1.f + expf(-v));
    }
    __syncthreads();
    float a0 = 0.f, a1 = 0.f, a2 = 0.f, a3 = 0.f;
    for (int d = 0; d < DD; d += 4) {
        a0 += sc[d+0] * W_ada[(size_t)(d+0)*SIXD + col];
        a1 += sc[d+1] * W_ada[(size_t)(d+1)*SIXD + col];
        a2 += sc[d+2] * W_ada[(size_t)(d+2)*SIXD + col];
        a3 += sc[d+3] * W_ada[(size_t)(d+3)*SIXD + col];
    }
    mods[b*SIXD + col] = b_ada[col] + ((a0 + a1) + (a2 + a3));
}

// 2 rows/block, shfl reduction.
template<bool RES>
__global__ void ln_mod_kernel(const float* __restrict__ in, const float* __restrict__ ao,
                              float* __restrict__ out,
                              const float* __restrict__ w, const float* __restrict__ bb,
                              const float* __restrict__ mods, int sh_ofs, int sc_ofs) {
    int half = threadIdx.x >> 7;
    int t    = threadIdx.x & 127;
    int row  = blockIdx.x * 2 + half;
    int bat  = row >> 10;
    const float* x = in + (size_t)row * DD;
    const float* mrow = mods + bat * SIXD;
    float v0 = x[t], v1 = x[t + 128], v2 = x[t + 256], v3 = x[t + 384];
    if (RES) {
        const float* a = ao + (size_t)row * DD;
        v0 += mrow[2*DD + t]       * a[t];
        v1 += mrow[2*DD + t + 128] * a[t + 128];
        v2 += mrow[2*DD + t + 256] * a[t + 256];
        v3 += mrow[2*DD + t + 384] * a[t + 384];
    }
    __shared__ float part[2][4];
    __shared__ float stat[2][2];
    int wsub = (threadIdx.x >> 5) & 3;
    int lane = threadIdx.x & 31;
    float s = (v0 + v1) + (v2 + v3);
    #pragma unroll
    for (int o = 16; o; o >>= 1) s += __shfl_down_sync(0xffffffffu, s, o);
    if (!lane) part[half][wsub] = s;
    __syncthreads();
    if (t == 0)
        stat[half][0] = ((part[half][0] + part[half][1]) + (part[half][2] + part[half][3])) * (1.f / DD);
    __syncthreads();
    float m = stat[half][0];
    float d0 = v0 - m, d1 = v1 - m, d2 = v2 - m, d3 = v3 - m;
    float qq = (d0*d0 + d1*d1) + (d2*d2 + d3*d3);
    #pragma unroll
    for (int o = 16; o; o >>= 1) qq += __shfl_down_sync(0xffffffffu, qq, o);
    if (!lane) part[half][wsub] = qq;
    __syncthreads();
    if (t == 0)
        stat[half][1] = rsqrtf(((part[half][0] + part[half][1]) + (part[half][2] + part[half][3])) * (1.f / DD) + 1e-5f);
    __syncthreads();
    float inv = stat[half][1];
    float* op = out + (size_t)row * DD;
    #pragma unroll
    for (int j = 0; j < 4; j++) {
        int i = t + j * 128;
        float dd = (j == 0 ? d0 : j == 1 ? d1 : j == 2 ? d2 : d3);
        float y = dd * inv * w[i] + bb[i];
        op[i] = y * (1.f + mrow[sc_ofs + i]) + mrow[sh_ofs + i];
    }
}

// per-row LN stats for BOTH q and k in one launch: blocks [0,TT/2) -> q, rest -> k.
__global__ void row_stats_qk_kernel(const float* __restrict__ qa, const float* __restrict__ ka,
                                    float2* __restrict__ qst, float2* __restrict__ kst) {
    int bi = blockIdx.x;
    const float* a;
    float2* st;
    int rowbase;
    if (bi < TT/2) { a = qa; st = qst; rowbase = bi * 2; }
    else           { a = ka; st = kst; rowbase = (bi - TT/2) * 2; }
    int half = threadIdx.x >> 7;
    int t    = threadIdx.x & 127;
    int row  = rowbase + half;
    const float* x = a + (size_t)row * DD;
    float v0 = x[t], v1 = x[t + 128], v2 = x[t + 256], v3 = x[t + 384];
    __shared__ float part[2][4];
    __shared__ float mean_s[2];
    int wsub = (threadIdx.x >> 5) & 3;
    int lane = threadIdx.x & 31;
    float s = (v0 + v1) + (v2 + v3);
    #pragma unroll
    for (int o = 16; o; o >>= 1) s += __shfl_down_sync(0xffffffffu, s, o);
    if (!lane) part[half][wsub] = s;
    __syncthreads();
    if (t == 0)
        mean_s[half] = ((part[half][0] + part[half][1]) + (part[half][2] + part[half][3])) * (1.f / DD);
    __syncthreads();
    float m = mean_s[half];
    float d0 = v0 - m, d1 = v1 - m, d2 = v2 - m, d3 = v3 - m;
    float qq = (d0*d0 + d1*d1) + (d2*d2 + d3*d3);
    #pragma unroll
    for (int o = 16; o; o >>= 1) qq += __shfl_down_sync(0xffffffffu, qq, o);
    if (!lane) part[half][wsub] = qq;
    __syncthreads();
    if (t == 0) {
        float inv = rsqrtf(((part[half][0] + part[half][1]) + (part[half][2] + part[half][3])) * (1.f / DD) + 1e-5f);
        st[row] = make_float2(m, inv);
    }
}

// fused LN-apply + transpose: dst[b][d][s] = (src[b][s][d]-m_s)*inv_s*w[d]+b[d].
__global__ void transpose_ln_kernel(const float* __restrict__ qsrc, const float* __restrict__ ksrc,
                                    float* __restrict__ qdst, float* __restrict__ kdst,
                                    const float2* __restrict__ qst, const float2* __restrict__ kst,
                                    const float* __restrict__ qw, const float* __restrict__ qb,
                                    const float* __restrict__ kw, const float* __restrict__ kb) {
    __shared__ float tbuf[32][33];
    __shared__ float2 sst[32];
    int z = blockIdx.z;
    bool isK = (z >= BB);
    int b = isK ? z - BB : z;
    const float* src = (isK ? ksrc : qsrc) + (size_t)b * SS * DD;
    float* dst       = (isK ? kdst : qdst) + (size_t)b * DD * SS;
    const float2* st = (isK ? kst : qst) + b * SS;
    const float* w   = isK ? kw : qw;
    const float* bbv = isK ? kb : qb;
    int d0 = blockIdx.x * 32;
    int s0 = blockIdx.y * 32;
    int x = threadIdx.x, y = threadIdx.y;
    if (threadIdx.y == 0) sst[x] = st[s0 + x];
    __syncthreads();
    float wv = w[d0 + x], bv = bbv[d0 + x];
    #pragma unroll
    for (int j = 0; j < 32; j += 8) {
        float v = src[(size_t)(s0 + y + j) * DD + d0 + x];
        float2 ms = sst[y + j];
        tbuf[y + j][x] = (v - ms.x) * ms.y * wv + bv;
    }
    __syncthreads();
    #pragma unroll
    for (int j = 0; j < 32; j += 8)
        dst[(size_t)(d0 + y + j) * SS + s0 + x] = tbuf[x][y + j];
}

// softmax over rows of 512; 2 rows/block, shfl; output pre-rounded to tf32
__global__ void softmax512_kernel(float* __restrict__ a) {
    int half = threadIdx.x >> 7;
    int t    = threadIdx.x & 127;
    float* row = a + (size_t)(blockIdx.x * 2 + half) * DD;
    float v0 = row[t], v1 = row[t + 128], v2 = row[t + 256], v3 = row[t + 384];
    __shared__ float part[2][4];
    __shared__ float stat[2];
    int wsub = (threadIdx.x >> 5) & 3;
    int lane = threadIdx.x & 31;
    float mx = fmaxf(fmaxf(v0, v1), fmaxf(v2, v3));
    #pragma unroll
    for (int o = 16; o; o >>= 1) mx = fmaxf(mx, __shfl_down_sync(0xffffffffu, mx, o));
    if (!lane) part[half][wsub] = mx;
    __syncthreads();
    if (t == 0)
        stat[half] = fmaxf(fmaxf(part[half][0], part[half][1]), fmaxf(part[half][2], part[half][3]));
    __syncthreads();
    float m = stat[half];
    float e0 = expf(v0 - m), e1 = expf(v1 - m), e2 = expf(v2 - m), e3 = expf(v3 - m);
    float s = (e0 + e1) + (e2 + e3);
    #pragma unroll
    for (int o = 16; o; o >>= 1) s += __shfl_down_sync(0xffffffffu, s, o);
    if (!lane) part[half][wsub] = s;
    __syncthreads();
    if (t == 0)
        stat[half] = 1.f / ((part[half][0] + part[half][1]) + (part[half][2] + part[half][3]));
    __syncthreads();
    float inv = stat[half];
    row[t]       = f2tf32f(e0 * inv);
    row[t + 128] = f2tf32f(e1 * inv);
    row[t + 256] = f2tf32f(e2 * inv);
    row[t + 384] = f2tf32f(e3 * inv);
}

__global__ void logits_kernel(const float* __restrict__ xm, const float* __restrict__ Wr,
                              const float* __restrict__ br, float* __restrict__ logits) {
    int t = blockIdx.x;
    __shared__ float s[DD];
    for (int i = threadIdx.x; i < DD; i += 256) s[i] = xm[(size_t)t*DD + i];
    __syncthreads();
    int w = threadIdx.x >> 5, lane = threadIdx.x & 31;
    float acc = 0.f;
    for (int d = lane; d < DD; d += 32) acc += s[d] * Wr[d*EE + w];
    for (int o = 16; o; o >>= 1) acc += __shfl_down_sync(0xffffffffu, acc, o);
    if (!lane) logits[t*EE + w] = acc + br[w];
}

__global__ void nrm_kernel(const float* __restrict__ logits, float* __restrict__ nrm) {
    int be = blockIdx.x, b = be >> 3, e = be & 7;
    int tid = threadIdx.x;
    float s = 0.f;
    for (int si = tid; si < SS; si += 256) {
        float v = logits[(size_t)((b << 10) + si)*EE + e];
        s += v * v;
    }
    __shared__ float red[256];
    red[tid] = s; __syncthreads();
    for (int o = 128; o; o >>= 1) { if (tid < o) red[tid] += red[tid + o]; __syncthreads(); }
    if (!tid) nrm[be] = sqrtf(red[0]);
}

__global__ void route_kernel(const float* __restrict__ logits, const float* __restrict__ nrm,
                             float* __restrict__ probs, int* __restrict__ cnt,
                             int* __restrict__ tokl, float* __restrict__ wtl) {
    int t = blockIdx.x * 128 + threadIdx.x;
    if (t >= TT) return;
    int b = t >> 10;
    float l[EE];
    float mx = -1e30f;
    #pragma unroll
    for (int e = 0; e < EE; e++) {
        l[e] = logits[t*EE + e] / fmaxf(nrm[b*EE + e], 1e-12f);
        mx = fmaxf(mx, l[e]);
    }
    float sum = 0.f;
    #pragma unroll
    for (int e = 0; e < EE; e++) { l[e] = expf(l[e] - mx); sum += l[e]; }
    float inv = 1.f / sum;
    #pragma unroll
    for (int e = 0; e < EE; e++) { l[e] *= inv; probs[t*EE + e] = l[e]; }
    int i0 = 0;
    #pragma unroll
    for (int e = 1; e < EE; e++) if (l[e] > l[i0]) i0 = e;
    int i1 = -1;
    #pragma unroll
    for (int e = 0; e < EE; e++) {
        if (e == i0) continue;
        if (i1 < 0 || l[e] > l[i1]) i1 = e;
    }
    int p0 = atomicAdd(&cnt[i0], 1);
    tokl[i0*TT + p0] = t; wtl[i0*TT + p0] = l[i0];
    int p1 = atomicAdd(&cnt[i1], 1);
    tokl[i1*TT + p1] = t; wtl[i1*TT + p1] = l[i1];
}

__global__ void offsets_kernel(const int* __restrict__ cnt, int* __restrict__ off) {
    if (threadIdx.x == 0) {
        int a = 0;
        for (int e = 0; e < EE; e++) { off[e] = a; a += cnt[e]; }
    }
}

// 32x32 tiled transpose, per z-slice.  RND: pre-round to tf32.
template<bool RND>
__global__ void transpose_kernel(const float* __restrict__ src, float* __restrict__ dst,
                                 int R, int C) {
    __shared__ float t[32][33];
    size_t eb = (size_t)blockIdx.z * R * C;
    int c0 = blockIdx.x * 32, r0 = blockIdx.y * 32;
    int x = threadIdx.x, y = threadIdx.y;
    #pragma unroll
    for (int j = 0; j < 32; j += 8) {
        float v = src[eb + (size_t)(r0 + y + j) * C + c0 + x];
        t[y + j][x] = RND ? f2tf32f(v) : v;
    }
    __syncthreads();
    #pragma unroll
    for (int j = 0; j < 32; j += 8)
        dst[eb + (size_t)(c0 + y + j) * R + r0 + x] = t[x][y + j];
}

// merged 4x DxD transpose: z=0..3 -> Wq,Wk,Wv (no round) | Wo (rounded)
__global__ void transpose4_kernel(const float* __restrict__ Wq, const float* __restrict__ Wk,
                                  const float* __restrict__ Wv, const float* __restrict__ Wo,
                                  float* __restrict__ wqkvt, float* __restrict__ wot) {
    __shared__ float t[32][33];
    int z = blockIdx.z;
    const float* src = (z == 0) ? Wq : (z == 1) ? Wk : (z == 2) ? Wv : Wo;
    float* dst = (z == 3) ? wot : (wqkvt + (size_t)z * DD * DD);
    bool rnd = (z == 3);
    int c0 = blockIdx.x * 32, r0 = blockIdx.y * 32;
    int x = threadIdx.x, y = threadIdx.y;
    #pragma unroll
    for (int j = 0; j < 32; j += 8) {
        float v = src[(size_t)(r0 + y + j) * DD + c0 + x];
        t[y + j][x] = rnd ? f2tf32f(v) : v;
    }
    __syncthreads();
    #pragma unroll
    for (int j = 0; j < 32; j += 8)
        dst[(size_t)(c0 + y + j) * DD + r0 + x] = t[x][y + j];
}

// dual transpose: W1 & W3 in one pass, pre-rounded to tf32
__global__ void transpose13_kernel(const float* __restrict__ s1, const float* __restrict__ s3,
                                   float* __restrict__ d1, float* __restrict__ d3,
                                   int R, int C) {
    __shared__ float t1[32][33];
    __shared__ float t3[32][33];
    size_t eb = (size_t)blockIdx.z * R * C;
    int c0 = blockIdx.x * 32, r0 = blockIdx.y * 32;
    int x = threadIdx.x, y = threadIdx.y;
    #pragma unroll
    for (int j = 0; j < 32; j += 8) {
        size_t si = eb + (size_t)(r0 + y + j) * C + c0 + x;
        t1[y + j][x] = f2tf32f(s1[si]);
        t3[y + j][x] = f2tf32f(s3[si]);
    }
    __syncthreads();
    #pragma unroll
    for (int j = 0; j < 32; j += 8) {
        size_t di = eb + (size_t)(c0 + y + j) * R + r0 + x;
        d1[di] = t1[x][y + j];
        d3[di] = t3[x][y + j];
    }
}

// ============ bf16 3-pass "fp32-equivalent" GEMM: C = A @ Bt^T ============
// MODE 0: dense batched (strides).  MODE 1: QKV split write (V pre-rounded to tf32).
template<int MODE, int NI>
__global__ void __launch_bounds__(256, 2)
b163_gemm_kernel(const float* __restrict__ A, const float* __restrict__ Bt,
                 float* __restrict__ C, int K, int N,
                 size_t sA, size_t sB, size_t sC,
                 float* __restrict__ Qo, float* __restrict__ Ko, float* __restrict__ Vo) {
    constexpr int NT = NI * 16;
    __shared__ uint32_t Ah[128][12], Al[128][12];
    __shared__ uint32_t Bh[NT][12],  Bl[NT][12];

    const int tid = threadIdx.x;
    const int n0 = blockIdx.x * NT;
    const int m0 = blockIdx.y * 128;
    if (MODE == 0) {
        A += blockIdx.z * sA; Bt += blockIdx.z * sB; C += blockIdx.z * sC;
    }

    const int wid = tid >> 5, lid = tid & 31;
    const int w_m = (wid & 3) * 32, w_n = (wid >> 2) * (NI * 8);
    const int lq = lid >> 2, lr = lid & 3;
    const int rowA = tid >> 1, cA = (tid & 1) * 8;
    const int rowB = (NI == 8) ? (tid >> 1) : (tid >> 2);
    const int cB   = (NI == 8) ? ((tid & 1) * 8) : ((tid & 3) * 4);

    float acc[2][NI][4];
    #pragma unroll
    for (int i = 0; i < 2; i++)
        #pragma unroll
        for (int j = 0; j < NI; j++)
            #pragma unroll
            for (int l = 0; l < 4; l++) acc[i][j][l] = 0.f;

    float4 ra0, ra1, rb0, rb1;
    auto LDG = [&](int t) {
        const float* ap = A + (size_t)(m0 + rowA) * K + t*16 + cA;
        ra0 = *(const float4*)ap; ra1 = *(const float4*)(ap + 4);
        const float* bp = Bt + (size_t)(n0 + rowB) * K + t*16 + cB;
        rb0 = *(const float4*)bp;
        if (NI == 8) rb1 = *(const float4*)(bp + 4);
    };

    const int NK = K / 16;
    LDG(0);
    for (int i = 0; i < NK; i++) {
        {
            uint32_t* aph = &Ah[rowA][cA/2];
            uint32_t* apl = &Al[rowA][cA/2];
            split2(ra0.x, ra0.y, aph[0], apl[0]);
            split2(ra0.z, ra0.w, aph[1], apl[1]);
            split2(ra1.x, ra1.y, aph[2], apl[2]);
            split2(ra1.z, ra1.w, aph[3], apl[3]);
            uint32_t* bph = &Bh[rowB][cB/2];
            uint32_t* bpl = &Bl[rowB][cB/2];
            split2(rb0.x, rb0.y, bph[0], bpl[0]);
            split2(rb0.z, rb0.w, bph[1], bpl[1]);
            if (NI == 8) {
                split2(rb1.x, rb1.y, bph[2], bpl[2]);
                split2(rb1.z, rb1.w, bph[3], bpl[3]);
            }
        }
        __syncthreads();
        if (i + 1 < NK) LDG(i + 1);
        uint32_t ah[2][4], al[2][4];
        #pragma unroll
        for (int mi = 0; mi < 2; mi++) {
            int mr = w_m + mi*16 + lq;
            ah[mi][0] = Ah[mr    ][lr];     al[mi][0] = Al[mr    ][lr];
            ah[mi][1] = Ah[mr + 8][lr];     al[mi][1] = Al[mr + 8][lr];
            ah[mi][2] = Ah[mr    ][4 + lr]; al[mi][2] = Al[mr    ][4 + lr];
            ah[mi][3] = Ah[mr + 8][4 + lr]; al[mi][3] = Al[mr + 8][4 + lr];
        }
        #pragma unroll
        for (int ni = 0; ni < NI; ni++) {
            int nr = w_n + ni*8 + lq;
            uint32_t bh[2], bl[2];
            bh[0] = Bh[nr][lr]; bh[1] = Bh[nr][4 + lr];
            bl[0] = Bl[nr][lr]; bl[1] = Bl[nr][4 + lr];
            mma16n8k16bf(acc[0][ni], ah[0], bh);
            mma16n8k16bf(acc[1][ni], ah[1], bh);
            mma16n8k16bf(acc[0][ni], ah[0], bl);
            mma16n8k16bf(acc[1][ni], ah[1], bl);
            mma16n8k16bf(acc[0][ni], al[0], bh);
            mma16n8k16bf(acc[1][ni], al[1], bh);
        }
        __syncthreads();
    }

    float* base = C;
    int csub = 0;
    bool isV = false;
    if (MODE == 1) {
        if (n0 < 512)       { base = Qo; csub = 0; }
        else if (n0 < 1024) { base = Ko; csub = 512; }
        else                { base = Vo; csub = 1024; isV = true; }
    }
    #pragma unroll
    for (int mi = 0; mi < 2; mi++) {
        #pragma unroll
        for (int half = 0; half < 2; half++) {
            int r = w_m + mi*16 + lq + half*8;
            #pragma unroll
            for (int ni = 0; ni < NI; ni++) {
                float v0 = acc[mi][ni][half*2 + 0];
                float v1 = acc[mi][ni][half*2 + 1];
                int col = w_n + ni*8 + 2*lr;
                if (MODE == 0) {
                    float* cp = C + (size_t)(m0 + r) * N + n0 + col;
                    cp[0] = v0; cp[1] = v1;
                } else {
                    float* cp = base + (size_t)(m0 + r) * DD + (n0 - csub) + col;
                    if (isV) { cp[0] = f2tf32f(v0); cp[1] = f2tf32f(v1); }
                    else     { cp[0] = v0;          cp[1] = v1; }
                }
            }
        }
    }
}

// ============ tf32 mma.sync GEMM: pre-rounded inputs, raw bit copy ============
template<int MODE, int NI, bool CVTOUT>
__global__ void __launch_bounds__(256, 2)
tf32_gemm_kernel(const float* __restrict__ A, const float* __restrict__ Bt,
                 float* __restrict__ C, int K, int N, int ldA,
                 size_t sA, size_t sB, size_t sC,
                 const int* __restrict__ cnt, const int* __restrict__ off,
                 const int* __restrict__ tokl, const float* __restrict__ wtl) {
    constexpr int NT = NI * 16;
    __shared__ uint32_t As[128][36];
    __shared__ uint32_t Bs[NT][36];
    __shared__ int stok[128];
    __shared__ float swt[128];

    const int tid = threadIdx.x;
    const int n0 = blockIdx.x * NT;
    int m0 = 0, count = 0, t0 = 0, gbase = 0;

    if (MODE == 0) {
        m0 = blockIdx.y * 128;
        A += blockIdx.z * sA; Bt += blockIdx.z * sB; C += blockIdx.z * sC;
    } else {
        const int e = blockIdx.z;
        count = cnt[e];
        t0 = blockIdx.y * 128;
        if (t0 >= count) return;
        gbase = off[e] + t0;
        if (tid < 128) {
            bool ok = (t0 + tid) < count;
            stok[tid] = ok ? tokl[e*TT + t0 + tid] : -1;
            swt[tid]  = ok ? wtl [e*TT + t0 + tid] : 0.f;
        }
        Bt += (size_t)e * N * K;
        __syncthreads();
    }

    const int wid = tid >> 5, lid = tid & 31;
    const int w_m = (wid & 3) * 32, w_n = (wid >> 2) * (NI * 8);
    const int lq = lid >> 2, lr = lid & 3;
    const int row_l = tid >> 3, c4 = tid & 7;

    float acc[2][NI][4];
    #pragma unroll
    for (int i = 0; i < 2; i++)
        #pragma unroll
        for (int j = 0; j < NI; j++)
            #pragma unroll
            for (int l = 0; l < 4; l++) acc[i][j][l] = 0.f;

    float4 ra[4], rb[NI/2];
    auto LDG = [&](int t) {
        #pragma unroll
        for (int j = 0; j < 4; j++) {
            int row = row_l + j * 32;
            if (MODE == 0) {
                ra[j] = *(const float4*)(A + (size_t)(m0 + row) * ldA + t*32 + c4*4);
            } else {
                ra[j] = make_float4(0.f,0.f,0.f,0.f);
                if (t0 + row < count)
                    ra[j] = *(const float4*)(A + (size_t)(gbase + row) * K + t*32 + c4*4);
            }
        }
        #pragma unroll
        for (int j = 0; j < NI/2; j++) {
            int row = row_l + j * 32;
            rb[j] = *(const float4*)(Bt + (size_t)(n0 + row) * K + t*32 + c4*4);
        }
    };

    const int NK = K / 32;
    LDG(0);
    for (int i = 0; i < NK; i++) {
        #pragma unroll
        for (int j = 0; j < 4; j++) {
            int row = row_l + j * 32;
            uint32_t* ap = &As[row][c4*4];
            ap[0] = __float_as_uint(ra[j].x); ap[1] = __float_as_uint(ra[j].y);
            ap[2] = __float_as_uint(ra[j].z); ap[3] = __float_as_uint(ra[j].w);
        }
        #pragma unroll
        for (int j = 0; j < NI/2; j++) {
            int row = row_l + j * 32;
            uint32_t* bp = &Bs[row][c4*4];
            bp[0] = __float_as_uint(rb[j].x); bp[1] = __float_as_uint(rb[j].y);
            bp[2] = __float_as_uint(rb[j].z); bp[3] = __float_as_uint(rb[j].w);
        }
        __syncthreads();
        if (i + 1 < NK) LDG(i + 1);
        #pragma unroll
        for (int ks = 0; ks < 32; ks += 8) {
            uint32_t af[2][4], bf[NI][2];
            #pragma unroll
            for (int mi = 0; mi < 2; mi++) {
                int mr = w_m + mi*16 + lq;
                af[mi][0] = As[mr    ][ks + lr];
                af[mi][1] = As[mr + 8][ks + lr];
                af[mi][2] = As[mr    ][ks + 4 + lr];
                af[mi][3] = As[mr + 8][ks + 4 + lr];
            }
            #pragma unroll
            for (int ni = 0; ni < NI; ni++) {
                int nr = w_n + ni*8 + lq;
                bf[ni][0] = Bs[nr][ks + lr];
                bf[ni][1] = Bs[nr][ks + 4 + lr];
            }
            #pragma unroll
            for (int mi = 0; mi < 2; mi++)
                #pragma unroll
                for (int ni = 0; ni < NI; ni++)
                    mma16n8k8(acc[mi][ni], af[mi], bf[ni]);
        }
        __syncthreads();
    }

    #pragma unroll
    for (int mi = 0; mi < 2; mi++) {
        #pragma unroll
        for (int half = 0; half < 2; half++) {
            int r = w_m + mi*16 + lq + half*8;
            #pragma unroll
            for (int ni = 0; ni < NI; ni++) {
                float v0 = acc[mi][ni][half*2 + 0];
                float v1 = acc[mi][ni][half*2 + 1];
                int col = w_n + ni*8 + 2*lr;
                if (MODE == 0) {
                    float* cp = C + (size_t)(m0 + r) * N + n0 + col;
                    if (CVTOUT) { cp[0] = f2tf32f(v0); cp[1] = f2tf32f(v1); }
                    else        { cp[0] = v0;          cp[1] = v1; }
                } else {
                    if (t0 + r < count) {
                        int tk = stok[r];
                        float wt = swt[r];
                        float* op = C + (size_t)tk * DD + n0 + col;
                        atomicAdd(op + 0, wt * v0);
                        atomicAdd(op + 1, wt * v1);
                    }
                }
            }
        }
    }
}

// ============ fused MoE up: G = sin(xm@W1t^T) * (xm@W3t^T) ============
// Tile 128x64 (NI=4): acc regs halved -> 2 CTAs/SM. K-order per element
// unchanged vs NI=8 -> bit-identical G. Static smem (36.9 KB/CTA).
__global__ void __launch_bounds__(256, 2)
moe_up_fused_kernel(const float* __restrict__ xm,
                    const float* __restrict__ B1t, const float* __restrict__ B3t,
                    float* __restrict__ G,
                    const int* __restrict__ cnt, const int* __restrict__ off,
                    const int* __restrict__ tokl) {
    __shared__ uint32_t As[128][36];
    __shared__ uint32_t B1s[64][36];
    __shared__ uint32_t B3s[64][36];
    __shared__ int stok[128];

    const int tid = threadIdx.x;
    const int e = blockIdx.z;
    const int count = cnt[e];
    const int t0 = blockIdx.y * 128;
    if (t0 >= count) return;
    const int n0 = blockIdx.x * 64;
    const int gbase = off[e] + t0;
    if (tid < 128)
        stok[tid] = (t0 + tid < count) ? tokl[e*TT + t0 + tid] : -1;
    B1t += (size_t)e * HH * DD;
    B3t += (size_t)e * HH * DD;
    __syncthreads();

    const int wid = tid >> 5, lid = tid & 31;
    const int w_m = (wid & 3) * 32, w_n = (wid >> 2) * 32;
    const int lq = lid >> 2, lr = lid & 3;
    const int row_l = tid >> 3, c4 = tid & 7;   // A: rows row_l + j*32, B: rows row_l(+32)

    float acc1[2][4][4], acc3[2][4][4];
    #pragma unroll
    for (int i = 0; i < 2; i++)
        #pragma unroll
        for (int j = 0; j < 4; j++)
            #pragma unroll
            for (int l = 0; l < 4; l++) { acc1[i][j][l] = 0.f; acc3[i][j][l] = 0.f; }

    float4 ra[4], rb1[2], rb3[2];
    auto LDG = [&](int t) {
        #pragma unroll
        for (int j = 0; j < 4; j++) {
            int row = row_l + j * 32;
            int tk = stok[row];
            ra[j] = make_float4(0.f,0.f,0.f,0.f);
            if (tk >= 0)
                ra[j] = *(const float4*)(xm + (size_t)tk * DD + t*32 + c4*4);
        }
        #pragma unroll
        for (int j = 0; j < 2; j++) {
            int row = row_l + j * 32;
            rb1[j] = *(const float4*)(B1t + (size_t)(n0 + row) * DD + t*32 + c4*4);
            rb3[j] = *(const float4*)(B3t + (size_t)(n0 + row) * DD + t*32 + c4*4);
        }
    };

    const int NK = DD / 32;
    LDG(0);
    for (int i = 0; i < NK; i++) {
        #pragma unroll
        for (int j = 0; j < 4; j++) {
            int row = row_l + j * 32;
            uint32_t* ap = &As[row][c4*4];
            ap[0] = f2tf32(ra[j].x); ap[1] = f2tf32(ra[j].y);
            ap[2] = f2tf32(ra[j].z); ap[3] = f2tf32(ra[j].w);
        }
        #pragma unroll
        for (int j = 0; j < 2; j++) {
            int row = row_l + j * 32;
            uint32_t* b1p = &B1s[row][c4*4];
            uint32_t* b3p = &B3s[row][c4*4];
            b1p[0] = __float_as_uint(rb1[j].x); b1p[1] = __float_as_uint(rb1[j].y);
            b1p[2] = __float_as_uint(rb1[j].z); b1p[3] = __float_as_uint(rb1[j].w);
            b3p[0] = __float_as_uint(rb3[j].x); b3p[1] = __float_as_uint(rb3[j].y);
            b3p[2] = __float_as_uint(rb3[j].z); b3p[3] = __float_as_uint(rb3[j].w);
        }
        __syncthreads();
        if (i + 1 < NK) LDG(i + 1);
        #pragma unroll
        for (int ks = 0; ks < 32; ks += 8) {
            uint32_t af[2][4];
            #pragma unroll
            for (int mi = 0; mi < 2; mi++) {
                int mr = w_m + mi*16 + lq;
                af[mi][0] = As[mr    ][ks + lr];
                af[mi][1] = As[mr + 8][ks + lr];
                af[mi][2] = As[mr    ][ks + 4 + lr];
                af[mi][3] = As[mr + 8][ks + 4 + lr];
            }
            #pragma unroll
            for (int ni = 0; ni < 4; ni++) {
                int nr = w_n + ni*8 + lq;
                uint32_t b1[2], b3[2];
                b1[0] = B1s[nr][ks + lr]; b1[1] = B1s[nr][ks + 4 + lr];
                b3[0] = B3s[nr][ks + lr]; b3[1] = B3s[nr][ks + 4 + lr];
                mma16n8k8(acc1[0][ni], af[0], b1);
                mma16n8k8(acc1[1][ni], af[1], b1);
                mma16n8k8(acc3[0][ni], af[0], b3);
                mma16n8k8(acc3[1][ni], af[1], b3);
            }
        }
        __syncthreads();
    }

    #pragma unroll
    for (int mi = 0; mi < 2; mi++) {
        #pragma unroll
        for (int half = 0; half < 2; half++) {
            int r = w_m + mi*16 + lq + half*8;
            if (t0 + r < count) {
                float* gp = G + (size_t)(gbase + r) * HH + n0;
                #pragma unroll
                for (int ni = 0; ni < 4; ni++) {
                    int col = w_n + ni*8 + 2*lr;
                    gp[col + 0] = f2tf32f(sinf(acc1[mi][ni][half*2 + 0]) * acc3[mi][ni][half*2 + 0]);
                    gp[col + 1] = f2tf32f(sinf(acc1[mi][ni][half*2 + 1]) * acc3[mi][ni][half*2 + 1]);
                }
            }
        }
    }
}

__global__ void aux_kernel(const float* __restrict__ probs, float* __restrict__ out, int out_size) {
    __shared__ float red[256];
    int tid = threadIdx.x;
    float s = 0.f;
    for (int idx = tid; idx < SS*EE; idx += 256) {
        int srow = idx >> 3, e = idx & 7;
        float a = 0.f;
        #pragma unroll
        for (int b = 0; b < BB; b++)
            a += probs[(size_t)((b << 10) + srow)*EE + e];
        a *= 0.25f;
        float d = (1.f / EE) - a;
        s += d * d;
    }
    red[tid] = s; __syncthreads();
    for (int o = 128; o; o >>= 1) { if (tid < o) red[tid] += red[tid + o]; __syncthreads(); }
    if (!tid && out_size > TT*DD) out[TT*DD] = red[0];
}

// ---------------- host launcher ----------------
extern "C" void kernel_launch(void* const* d_in, const int* in_sizes, int n_in,
                              void* d_out, int out_size) {
    const float* x     = (const float*)d_in[0];
    const float* c     = (const float*)d_in[1];
    const float* W_ada = (const float*)d_in[2];
    const float* b_ada = (const float*)d_in[3];
    const float* Wq    = (const float*)d_in[4];
    const float* Wk    = (const float*)d_in[5];
    const float* Wv    = (const float*)d_in[6];
    const float* Wo    = (const float*)d_in[7];
    const float* qn_w  = (const float*)d_in[8];
    const float* qn_b  = (const float*)d_in[9];
    const float* kn_w  = (const float*)d_in[10];
    const float* kn_b  = (const float*)d_in[11];
    const float* an_w  = (const float*)d_in[12];
    const float* an_b  = (const float*)d_in[13];
    const float* fn_w  = (const float*)d_in[14];
    const float* fn_b  = (const float*)d_in[15];
    const float* Wr    = (const float*)d_in[16];
    const float* br    = (const float*)d_in[17];
    const float* W1    = (const float*)d_in[18];
    const float* W2    = (const float*)d_in[19];
    const float* W3    = (const float*)d_in[20];
    float* out = (float*)d_out;

    float* buf; cudaGetSymbolAddress((void**)&buf, g_buf);
    int* ibuf;  cudaGetSymbolAddress((void**)&ibuf, g_ibuf);

    float* mods   = buf + OF_MODS;
    float* h      = buf + OF_H;
    float* q      = buf + OF_Q;
    float* k      = buf + OF_K;
    float* v      = buf + OF_V;
    float* scores = buf + OF_SC;
    float* attn   = buf + OF_AT;
    float* attnO  = buf + OF_AO;
    float* xm     = buf + OF_XM;
    float* logits = buf + OF_LG;
    float* probs  = buf + OF_PR;
    float* nrm    = buf + OF_NRM;
    float* wtl    = buf + OF_WT;
    float2* qst   = (float2*)(buf + OF_QS);
    float2* kst   = (float2*)(buf + OF_KS);
    float* G      = buf + OF_G;
    float* w1t    = buf + OF_W1T;
    float* w3t    = buf + OF_W3T;
    float* w2t    = buf + OF_W2T;
    float* wqkvt  = buf + OF_WQKVT;
    float* wot    = buf + OF_WOT;
    float* qT     = buf + OF_QT;
    float* kT     = buf + OF_KT;
    int* cnt  = ibuf + IOF_CNT;
    int* off  = ibuf + IOF_OFF;
    int* tokl = ibuf + IOF_TOK;

    // 0. zero out + counters; weight transposes (pre-rounded where tf32-exclusive)
    zero_kernel<<<(TT*DD + 255)/256, 256>>>(out, cnt);
    transpose13_kernel<<<dim3(HH/32, DD/32, EE), dim3(32,8)>>>(W1, W3, w1t, w3t, DD, HH);
    transpose_kernel<true><<<dim3(DD/32, HH/32, EE), dim3(32,8)>>>(W2, w2t, HH, DD);
    transpose4_kernel<<<dim3(DD/32, DD/32, 4), dim3(32,8)>>>(Wq, Wk, Wv, Wo, wqkvt, wot);

    // 1. adaLN mods
    mods_kernel<<<dim3(BB, SIXD/256), 256>>>(c, W_ada, b_ada, mods);

    // 2. h = modulate(LN(x; an), sh_msa, sc_msa)
    ln_mod_kernel<false><<<TT/2, 256>>>(x, nullptr, h, an_w, an_b, mods, 0, DD);

    // 3. fused QKV projection — bf16 3-pass; V output pre-rounded to tf32
    b163_gemm_kernel<1,8><<<dim3(3*DD/128, TT/128), 256>>>(h, wqkvt, nullptr, DD, 3*DD,
                                                           0,0,0, q, k, v);

    // 4. LN stats for q & k (single launch), then fused LN-apply + transpose
    row_stats_qk_kernel<<<TT, 256>>>(q, k, qst, kst);
    transpose_ln_kernel<<<dim3(DD/32, SS/32, 2*BB), dim3(32,8)>>>(q, k, qT, kT, qst, kst,
                                                                  qn_w, qn_b, kn_w, kn_b);

    // 5. scores[b] = qT[b] @ kT[b]^T — bf16 3-pass, N64 tiles
    b163_gemm_kernel<0,4><<<dim3(DD/64, DD/128, BB), 256>>>(qT, kT, scores, SS, DD,
                                                            (size_t)DD*SS, (size_t)DD*SS,
                                                            (size_t)DD*DD,
                                                            nullptr, nullptr, nullptr);

    // 6. softmax rows of 512 (shfl; output pre-rounded to tf32)
    softmax512_kernel<<<BB*DD/2, 256>>>(scores);

    // 7. attn = v @ A^T — tf32, output pre-rounded
    tf32_gemm_kernel<0,4,true><<<dim3(DD/64, SS/128, BB), 256>>>(v, scores, attn, DD, DD, DD,
                                                                 (size_t)SS*DD, (size_t)DD*DD,
                                                                 (size_t)SS*DD, 0,0,0,0);

    // 8. attnO = attn @ Wo — tf32, fp32 output
    tf32_gemm_kernel<0,4,false><<<dim3(DD/64, TT/128, 1), 256>>>(attn, wot, attnO, DD, DD, DD,
                                                                 0,0,0, 0,0,0,0);

    // 9+10. xm = modulate(LN(x + g_msa*attnO; fn), sh_mlp, sc_mlp)
    ln_mod_kernel<true><<<TT/2, 256>>>(x, attnO, xm, fn_w, fn_b, mods, 3*DD, 4*DD);

    // 11-14. routing
    logits_kernel<<<TT, 256>>>(xm, Wr, br, logits);
    nrm_kernel<<<BB*EE, 256>>>(logits, nrm);
    route_kernel<<<TT/128, 128>>>(logits, nrm, probs, cnt, tokl, wtl);
    offsets_kernel<<<1, 32>>>(cnt, off);

    // 15. fused MoE up: G = sin(xm@W1^T) * (xm@W3^T) — 128x64 tiles, 2 CTAs/SM
    moe_up_fused_kernel<<<dim3(HH/64, TT/128, EE), 256>>>(xm, w1t, w3t, G, cnt, off, tokl);

    // 16. MoE down: out += wt * (G @ W2^T)
    tf32_gemm_kernel<3,8,false><<<dim3(DD/128, TT/128, EE), 256>>>(G, w2t, out, HH, DD, HH,
                                                                   0,0,0, cnt, off, tokl, wtl);

    // 17. aux loss
    aux_kernel<<<1, 256>>>(probs, out, out_size);
}

// round 16
// speedup vs baseline: 1.0743x; 1.0131x over previous
#include <cuda_runtime.h>
#include <cuda_bf16.h>
#include <math.h>
#include <stdint.h>

// Problem constants
#define BB 4
#define SS 1024
#define DD 512
#define EE 8
#define HH 1536
#define TT (BB*SS)          // 4096 tokens
#define SIXD (6*DD)         // 3072

// ---------------- scratch (device globals; no runtime allocation) ----------------
#define OF_MODS 0                            // B*6D
#define OF_H    (OF_MODS + BB*SIXD)          // T*D
#define OF_Q    (OF_H  + TT*DD)
#define OF_K    (OF_Q  + TT*DD)
#define OF_V    (OF_K  + TT*DD)
#define OF_SC   (OF_V  + TT*DD)              // B*D*D
#define OF_AT   (OF_SC + BB*DD*DD)           // T*D  (also scores split-1 partial)
#define OF_AO   (OF_AT + TT*DD)
#define OF_XM   (OF_AO + TT*DD)
#define OF_LG   (OF_XM + TT*DD)              // T*E
#define OF_PR   (OF_LG + TT*EE)              // T*E
#define OF_NRM  (OF_PR + TT*EE)              // B*E
#define OF_WT   (OF_NRM + BB*EE)             // E*T
#define OF_QS   (OF_WT + EE*TT)              // T*2 (q stats)
#define OF_KS   (OF_QS + 2*TT)               // T*2 (k stats)
#define OF_G    (OF_KS + 2*TT)               // 2T*H
#define OF_W1T  (OF_G + 2*TT*HH)             // E*H*D
#define OF_W3T  (OF_W1T + EE*HH*DD)
#define OF_W2T  (OF_W3T + EE*HH*DD)          // E*D*H
#define OF_WQKVT (OF_W2T + EE*DD*HH)         // 1536*512
#define OF_WOT  (OF_WQKVT + 3*DD*DD)         // D*D
#define OF_QT   (OF_WOT + DD*DD)             // B*D*S
#define OF_KT   (OF_QT + TT*DD)              // B*D*S
#define BUF_TOTAL (OF_KT + TT*DD)

__device__ __align__(256) float g_buf[BUF_TOTAL];

// int scratch: cnt(8) off(8) tok(E*T)
#define IOF_CNT 0
#define IOF_OFF 8
#define IOF_TOK 16
__device__ int g_ibuf[IOF_TOK + EE*TT];

// ---------------- helpers ----------------
__device__ __forceinline__ uint32_t f2tf32(float f) {
    uint32_t r;
    asm("cvt.rna.tf32.f32 %0, %1;" : "=r"(r) : "f"(f));
    return r;
}
__device__ __forceinline__ float f2tf32f(float f) {
    return __uint_as_float(f2tf32(f));
}
__device__ __forceinline__ void mma16n8k8(float* d, const uint32_t* a, const uint32_t* b) {
    asm volatile(
        "mma.sync.aligned.m16n8k8.row.col.f32.tf32.tf32.f32 "
        "{%0,%1,%2,%3}, {%4,%5,%6,%7}, {%8,%9}, {%0,%1,%2,%3};"
        : "+f"(d[0]), "+f"(d[1]), "+f"(d[2]), "+f"(d[3])
        : "r"(a[0]), "r"(a[1]), "r"(a[2]), "r"(a[3]), "r"(b[0]), "r"(b[1]));
}
__device__ __forceinline__ void mma16n8k16bf(float* d, const uint32_t* a, const uint32_t* b) {
    asm volatile(
        "mma.sync.aligned.m16n8k16.row.col.f32.bf16.bf16.f32 "
        "{%0,%1,%2,%3}, {%4,%5,%6,%7}, {%8,%9}, {%0,%1,%2,%3};"
        : "+f"(d[0]), "+f"(d[1]), "+f"(d[2]), "+f"(d[3])
        : "r"(a[0]), "r"(a[1]), "r"(a[2]), "r"(a[3]), "r"(b[0]), "r"(b[1]));
}
__device__ __forceinline__ void split2(float x, float y, uint32_t& hi, uint32_t& lo) {
    __nv_bfloat16 hx = __float2bfloat16_rn(x);
    __nv_bfloat16 hy = __float2bfloat16_rn(y);
    float rx = x - __bfloat162float(hx);
    float ry = y - __bfloat162float(hy);
    __nv_bfloat162 h2; h2.x = hx; h2.y = hy;
    __nv_bfloat162 l2; l2.x = __float2bfloat16_rn(rx); l2.y = __float2bfloat16_rn(ry);
    hi = *(uint32_t*)&h2;
    lo = *(uint32_t*)&l2;
}

// ---------------- elementwise / small kernels ----------------

__global__ void zero_kernel(float* out, int* cnt) {
    int i = blockIdx.x * 256 + threadIdx.x;
    if (i < TT*DD) out[i] = 0.f;
    if (i < EE) cnt[i] = 0;
}

__global__ void mods_kernel(const float* __restrict__ c,
                            const float* __restrict__ W_ada,
                            const float* __restrict__ b_ada,
                            float* __restrict__ mods) {
    int b   = blockIdx.x;
    int col = blockIdx.y * 256 + threadIdx.x;
    __shared__ float sc[DD];
    for (int i = threadIdx.x; i < DD; i += 256) {
        float v = c[b*DD + i];
        sc[i] = v / (1.f + expf(-v));
    }
    __syncthreads();
    float a0 = 0.f, a1 = 0.f, a2 = 0.f, a3 = 0.f;
    for (int d = 0; d < DD; d += 4) {
        a0 += sc[d+0] * W_ada[(size_t)(d+0)*SIXD + col];
        a1 += sc[d+1] * W_ada[(size_t)(d+1)*SIXD + col];
        a2 += sc[d+2] * W_ada[(size_t)(d+2)*SIXD + col];
        a3 += sc[d+3] * W_ada[(size_t)(d+3)*SIXD + col];
    }
    mods[b*SIXD + col] = b_ada[col] + ((a0 + a1) + (a2 + a3));
}

// 2 rows/block, shfl reduction.
template<bool RES>
__global__ void ln_mod_kernel(const float* __restrict__ in, const float* __restrict__ ao,
                              float* __restrict__ out,
                              const float* __restrict__ w, const float* __restrict__ bb,
                              const float* __restrict__ mods, int sh_ofs, int sc_ofs) {
    int half = threadIdx.x >> 7;
    int t    = threadIdx.x & 127;
    int row  = blockIdx.x * 2 + half;
    int bat  = row >> 10;
    const float* x = in + (size_t)row * DD;
    const float* mrow = mods + bat * SIXD;
    float v0 = x[t], v1 = x[t + 128], v2 = x[t + 256], v3 = x[t + 384];
    if (RES) {
        const float* a = ao + (size_t)row * DD;
        v0 += mrow[2*DD + t]       * a[t];
        v1 += mrow[2*DD + t + 128] * a[t + 128];
        v2 += mrow[2*DD + t + 256] * a[t + 256];
        v3 += mrow[2*DD + t + 384] * a[t + 384];
    }
    __shared__ float part[2][4];
    __shared__ float stat[2][2];
    int wsub = (threadIdx.x >> 5) & 3;
    int lane = threadIdx.x & 31;
    float s = (v0 + v1) + (v2 + v3);
    #pragma unroll
    for (int o = 16; o; o >>= 1) s += __shfl_down_sync(0xffffffffu, s, o);
    if (!lane) part[half][wsub] = s;
    __syncthreads();
    if (t == 0)
        stat[half][0] = ((part[half][0] + part[half][1]) + (part[half][2] + part[half][3])) * (1.f / DD);
    __syncthreads();
    float m = stat[half][0];
    float d0 = v0 - m, d1 = v1 - m, d2 = v2 - m, d3 = v3 - m;
    float qq = (d0*d0 + d1*d1) + (d2*d2 + d3*d3);
    #pragma unroll
    for (int o = 16; o; o >>= 1) qq += __shfl_down_sync(0xffffffffu, qq, o);
    if (!lane) part[half][wsub] = qq;
    __syncthreads();
    if (t == 0)
        stat[half][1] = rsqrtf(((part[half][0] + part[half][1]) + (part[half][2] + part[half][3])) * (1.f / DD) + 1e-5f);
    __syncthreads();
    float inv = stat[half][1];
    float* op = out + (size_t)row * DD;
    #pragma unroll
    for (int j = 0; j < 4; j++) {
        int i = t + j * 128;
        float dd = (j == 0 ? d0 : j == 1 ? d1 : j == 2 ? d2 : d3);
        float y = dd * inv * w[i] + bb[i];
        op[i] = y * (1.f + mrow[sc_ofs + i]) + mrow[sh_ofs + i];
    }
}

// per-row LN stats for BOTH q and k in one launch: blocks [0,TT/2) -> q, rest -> k.
__global__ void row_stats_qk_kernel(const float* __restrict__ qa, const float* __restrict__ ka,
                                    float2* __restrict__ qst, float2* __restrict__ kst) {
    int bi = blockIdx.x;
    const float* a;
    float2* st;
    int rowbase;
    if (bi < TT/2) { a = qa; st = qst; rowbase = bi * 2; }
    else           { a = ka; st = kst; rowbase = (bi - TT/2) * 2; }
    int half = threadIdx.x >> 7;
    int t    = threadIdx.x & 127;
    int row  = rowbase + half;
    const float* x = a + (size_t)row * DD;
    float v0 = x[t], v1 = x[t + 128], v2 = x[t + 256], v3 = x[t + 384];
    __shared__ float part[2][4];
    __shared__ float mean_s[2];
    int wsub = (threadIdx.x >> 5) & 3;
    int lane = threadIdx.x & 31;
    float s = (v0 + v1) + (v2 + v3);
    #pragma unroll
    for (int o = 16; o; o >>= 1) s += __shfl_down_sync(0xffffffffu, s, o);
    if (!lane) part[half][wsub] = s;
    __syncthreads();
    if (t == 0)
        mean_s[half] = ((part[half][0] + part[half][1]) + (part[half][2] + part[half][3])) * (1.f / DD);
    __syncthreads();
    float m = mean_s[half];
    float d0 = v0 - m, d1 = v1 - m, d2 = v2 - m, d3 = v3 - m;
    float qq = (d0*d0 + d1*d1) + (d2*d2 + d3*d3);
    #pragma unroll
    for (int o = 16; o; o >>= 1) qq += __shfl_down_sync(0xffffffffu, qq, o);
    if (!lane) part[half][wsub] = qq;
    __syncthreads();
    if (t == 0) {
        float inv = rsqrtf(((part[half][0] + part[half][1]) + (part[half][2] + part[half][3])) * (1.f / DD) + 1e-5f);
        st[row] = make_float2(m, inv);
    }
}

// fused LN-apply + transpose: dst[b][d][s] = (src[b][s][d]-m_s)*inv_s*w[d]+b[d].
__global__ void transpose_ln_kernel(const float* __restrict__ qsrc, const float* __restrict__ ksrc,
                                    float* __restrict__ qdst, float* __restrict__ kdst,
                                    const float2* __restrict__ qst, const float2* __restrict__ kst,
                                    const float* __restrict__ qw, const float* __restrict__ qb,
                                    const float* __restrict__ kw, const float* __restrict__ kb) {
    __shared__ float tbuf[32][33];
    __shared__ float2 sst[32];
    int z = blockIdx.z;
    bool isK = (z >= BB);
    int b = isK ? z - BB : z;
    const float* src = (isK ? ksrc : qsrc) + (size_t)b * SS * DD;
    float* dst       = (isK ? kdst : qdst) + (size_t)b * DD * SS;
    const float2* st = (isK ? kst : qst) + b * SS;
    const float* w   = isK ? kw : qw;
    const float* bbv = isK ? kb : qb;
    int d0 = blockIdx.x * 32;
    int s0 = blockIdx.y * 32;
    int x = threadIdx.x, y = threadIdx.y;
    if (threadIdx.y == 0) sst[x] = st[s0 + x];
    __syncthreads();
    float wv = w[d0 + x], bv = bbv[d0 + x];
    #pragma unroll
    for (int j = 0; j < 32; j += 8) {
        float v = src[(size_t)(s0 + y + j) * DD + d0 + x];
        float2 ms = sst[y + j];
        tbuf[y + j][x] = (v - ms.x) * ms.y * wv + bv;
    }
    __syncthreads();
    #pragma unroll
    for (int j = 0; j < 32; j += 8)
        dst[(size_t)(d0 + y + j) * SS + s0 + x] = tbuf[x][y + j];
}

// softmax over rows of 512; 2 rows/block, shfl.
// Reads scores = p0[row] + p1[row] (split-K partials), writes tf32-rounded to p0.
__global__ void softmax512_kernel(float* __restrict__ a, const float* __restrict__ p2) {
    int half = threadIdx.x >> 7;
    int t    = threadIdx.x & 127;
    size_t ro = (size_t)(blockIdx.x * 2 + half) * DD;
    float* row = a + ro;
    const float* row2 = p2 + ro;
    float v0 = row[t]       + row2[t];
    float v1 = row[t + 128] + row2[t + 128];
    float v2 = row[t + 256] + row2[t + 256];
    float v3 = row[t + 384] + row2[t + 384];
    __shared__ float part[2][4];
    __shared__ float stat[2];
    int wsub = (threadIdx.x >> 5) & 3;
    int lane = threadIdx.x & 31;
    float mx = fmaxf(fmaxf(v0, v1), fmaxf(v2, v3));
    #pragma unroll
    for (int o = 16; o; o >>= 1) mx = fmaxf(mx, __shfl_down_sync(0xffffffffu, mx, o));
    if (!lane) part[half][wsub] = mx;
    __syncthreads();
    if (t == 0)
        stat[half] = fmaxf(fmaxf(part[half][0], part[half][1]), fmaxf(part[half][2], part[half][3]));
    __syncthreads();
    float m = stat[half];
    float e0 = expf(v0 - m), e1 = expf(v1 - m), e2 = expf(v2 - m), e3 = expf(v3 - m);
    float s = (e0 + e1) + (e2 + e3);
    #pragma unroll
    for (int o = 16; o; o >>= 1) s += __shfl_down_sync(0xffffffffu, s, o);
    if (!lane) part[half][wsub] = s;
    __syncthreads();
    if (t == 0)
        stat[half] = 1.f / ((part[half][0] + part[half][1]) + (part[half][2] + part[half][3]));
    __syncthreads();
    float inv = stat[half];
    row[t]       = f2tf32f(e0 * inv);
    row[t + 128] = f2tf32f(e1 * inv);
    row[t + 256] = f2tf32f(e2 * inv);
    row[t + 384] = f2tf32f(e3 * inv);
}

__global__ void logits_kernel(const float* __restrict__ xm, const float* __restrict__ Wr,
                              const float* __restrict__ br, float* __restrict__ logits) {
    int t = blockIdx.x;
    __shared__ float s[DD];
    for (int i = threadIdx.x; i < DD; i += 256) s[i] = xm[(size_t)t*DD + i];
    __syncthreads();
    int w = threadIdx.x >> 5, lane = threadIdx.x & 31;
    float acc = 0.f;
    for (int d = lane; d < DD; d += 32) acc += s[d] * Wr[d*EE + w];
    for (int o = 16; o; o >>= 1) acc += __shfl_down_sync(0xffffffffu, acc, o);
    if (!lane) logits[t*EE + w] = acc + br[w];
}

__global__ void nrm_kernel(const float* __restrict__ logits, float* __restrict__ nrm) {
    int be = blockIdx.x, b = be >> 3, e = be & 7;
    int tid = threadIdx.x;
    float s = 0.f;
    for (int si = tid; si < SS; si += 256) {
        float v = logits[(size_t)((b << 10) + si)*EE + e];
        s += v * v;
    }
    __shared__ float red[256];
    red[tid] = s; __syncthreads();
    for (int o = 128; o; o >>= 1) { if (tid < o) red[tid] += red[tid + o]; __syncthreads(); }
    if (!tid) nrm[be] = sqrtf(red[0]);
}

__global__ void route_kernel(const float* __restrict__ logits, const float* __restrict__ nrm,
                             float* __restrict__ probs, int* __restrict__ cnt,
                             int* __restrict__ tokl, float* __restrict__ wtl) {
    int t = blockIdx.x * 128 + threadIdx.x;
    if (t >= TT) return;
    int b = t >> 10;
    float l[EE];
    float mx = -1e30f;
    #pragma unroll
    for (int e = 0; e < EE; e++) {
        l[e] = logits[t*EE + e] / fmaxf(nrm[b*EE + e], 1e-12f);
        mx = fmaxf(mx, l[e]);
    }
    float sum = 0.f;
    #pragma unroll
    for (int e = 0; e < EE; e++) { l[e] = expf(l[e] - mx); sum += l[e]; }
    float inv = 1.f / sum;
    #pragma unroll
    for (int e = 0; e < EE; e++) { l[e] *= inv; probs[t*EE + e] = l[e]; }
    int i0 = 0;
    #pragma unroll
    for (int e = 1; e < EE; e++) if (l[e] > l[i0]) i0 = e;
    int i1 = -1;
    #pragma unroll
    for (int e = 0; e < EE; e++) {
        if (e == i0) continue;
        if (i1 < 0 || l[e] > l[i1]) i1 = e;
    }
    int p0 = atomicAdd(&cnt[i0], 1);
    tokl[i0*TT + p0] = t; wtl[i0*TT + p0] = l[i0];
    int p1 = atomicAdd(&cnt[i1], 1);
    tokl[i1*TT + p1] = t; wtl[i1*TT + p1] = l[i1];
}

__global__ void offsets_kernel(const int* __restrict__ cnt, int* __restrict__ off) {
    if (threadIdx.x == 0) {
        int a = 0;
        for (int e = 0; e < EE; e++) { off[e] = a; a += cnt[e]; }
    }
}

// 32x32 tiled transpose, per z-slice.  RND: pre-round to tf32.
template<bool RND>
__global__ void transpose_kernel(const float* __restrict__ src, float* __restrict__ dst,
                                 int R, int C) {
    __shared__ float t[32][33];
    size_t eb = (size_t)blockIdx.z * R * C;
    int c0 = blockIdx.x * 32, r0 = blockIdx.y * 32;
    int x = threadIdx.x, y = threadIdx.y;
    #pragma unroll
    for (int j = 0; j < 32; j += 8) {
        float v = src[eb + (size_t)(r0 + y + j) * C + c0 + x];
        t[y + j][x] = RND ? f2tf32f(v) : v;
    }
    __syncthreads();
    #pragma unroll
    for (int j = 0; j < 32; j += 8)
        dst[eb + (size_t)(c0 + y + j) * R + r0 + x] = t[x][y + j];
}

// merged 4x DxD transpose: z=0..3 -> Wq,Wk,Wv (no round) | Wo (rounded)
__global__ void transpose4_kernel(const float* __restrict__ Wq, const float* __restrict__ Wk,
                                  const float* __restrict__ Wv, const float* __restrict__ Wo,
                                  float* __restrict__ wqkvt, float* __restrict__ wot) {
    __shared__ float t[32][33];
    int z = blockIdx.z;
    const float* src = (z == 0) ? Wq : (z == 1) ? Wk : (z == 2) ? Wv : Wo;
    float* dst = (z == 3) ? wot : (wqkvt + (size_t)z * DD * DD);
    bool rnd = (z == 3);
    int c0 = blockIdx.x * 32, r0 = blockIdx.y * 32;
    int x = threadIdx.x, y = threadIdx.y;
    #pragma unroll
    for (int j = 0; j < 32; j += 8) {
        float v = src[(size_t)(r0 + y + j) * DD + c0 + x];
        t[y + j][x] = rnd ? f2tf32f(v) : v;
    }
    __syncthreads();
    #pragma unroll
    for (int j = 0; j < 32; j += 8)
        dst[(size_t)(c0 + y + j) * DD + r0 + x] = t[x][y + j];
}

// dual transpose: W1 & W3 in one pass, pre-rounded to tf32
__global__ void transpose13_kernel(const float* __restrict__ s1, const float* __restrict__ s3,
                                   float* __restrict__ d1, float* __restrict__ d3,
                                   int R, int C) {
    __shared__ float t1[32][33];
    __shared__ float t3[32][33];
    size_t eb = (size_t)blockIdx.z * R * C;
    int c0 = blockIdx.x * 32, r0 = blockIdx.y * 32;
    int x = threadIdx.x, y = threadIdx.y;
    #pragma unroll
    for (int j = 0; j < 32; j += 8) {
        size_t si = eb + (size_t)(r0 + y + j) * C + c0 + x;
        t1[y + j][x] = f2tf32f(s1[si]);
        t3[y + j][x] = f2tf32f(s3[si]);
    }
    __syncthreads();
    #pragma unroll
    for (int j = 0; j < 32; j += 8) {
        size_t di = eb + (size_t)(c0 + y + j) * R + r0 + x;
        d1[di] = t1[x][y + j];
        d3[di] = t3[x][y + j];
    }
}

// ============ bf16 3-pass "fp32-equivalent" GEMM: C = A @ Bt^T ============
// ldAB = row stride of A/Bt; K = loop extent.
// MODE 1: QKV split write (V pre-rounded to tf32).
// MODE 2: split-K scores: z=b*2+split; k-offset split*K; plain store into
//         per-split partial buffer (C for split 0, Qo for split 1).
template<int MODE, int NI>
__global__ void __launch_bounds__(256, 2)
b163_gemm_kernel(const float* __restrict__ A, const float* __restrict__ Bt,
                 float* __restrict__ C, int K, int N, int ldAB,
                 size_t sA, size_t sB, size_t sC,
                 float* __restrict__ Qo, float* __restrict__ Ko, float* __restrict__ Vo) {
    constexpr int NT = NI * 16;
    __shared__ uint32_t Ah[128][12], Al[128][12];
    __shared__ uint32_t Bh[NT][12],  Bl[NT][12];

    const int tid = threadIdx.x;
    const int n0 = blockIdx.x * NT;
    const int m0 = blockIdx.y * 128;
    int splitz = 0;
    if (MODE == 2) {
        int b = blockIdx.z >> 1;
        splitz = blockIdx.z & 1;
        A += b * sA + (size_t)splitz * K;
        Bt += b * sB + (size_t)splitz * K;
        C += b * sC;
        Qo += b * sC;
    }

    const int wid = tid >> 5, lid = tid & 31;
    const int w_m = (wid & 3) * 32, w_n = (wid >> 2) * (NI * 8);
    const int lq = lid >> 2, lr = lid & 3;
    const int rowA = tid >> 1, cA = (tid & 1) * 8;
    const int rowB = (NI == 8) ? (tid >> 1) : (tid >> 2);
    const int cB   = (NI == 8) ? ((tid & 1) * 8) : ((tid & 3) * 4);

    float acc[2][NI][4];
    #pragma unroll
    for (int i = 0; i < 2; i++)
        #pragma unroll
        for (int j = 0; j < NI; j++)
            #pragma unroll
            for (int l = 0; l < 4; l++) acc[i][j][l] = 0.f;

    float4 ra0, ra1, rb0, rb1;
    auto LDG = [&](int t) {
        const float* ap = A + (size_t)(m0 + rowA) * ldAB + t*16 + cA;
        ra0 = *(const float4*)ap; ra1 = *(const float4*)(ap + 4);
        const float* bp = Bt + (size_t)(n0 + rowB) * ldAB + t*16 + cB;
        rb0 = *(const float4*)bp;
        if (NI == 8) rb1 = *(const float4*)(bp + 4);
    };

    const int NK = K / 16;
    LDG(0);
    for (int i = 0; i < NK; i++) {
        {
            uint32_t* aph = &Ah[rowA][cA/2];
            uint32_t* apl = &Al[rowA][cA/2];
            split2(ra0.x, ra0.y, aph[0], apl[0]);
            split2(ra0.z, ra0.w, aph[1], apl[1]);
            split2(ra1.x, ra1.y, aph[2], apl[2]);
            split2(ra1.z, ra1.w, aph[3], apl[3]);
            uint32_t* bph = &Bh[rowB][cB/2];
            uint32_t* bpl = &Bl[rowB][cB/2];
            split2(rb0.x, rb0.y, bph[0], bpl[0]);
            split2(rb0.z, rb0.w, bph[1], bpl[1]);
            if (NI == 8) {
                split2(rb1.x, rb1.y, bph[2], bpl[2]);
                split2(rb1.z, rb1.w, bph[3], bpl[3]);
            }
        }
        __syncthreads();
        if (i + 1 < NK) LDG(i + 1);
        uint32_t ah[2][4], al[2][4];
        #pragma unroll
        for (int mi = 0; mi < 2; mi++) {
            int mr = w_m + mi*16 + lq;
            ah[mi][0] = Ah[mr    ][lr];     al[mi][0] = Al[mr    ][lr];
            ah[mi][1] = Ah[mr + 8][lr];     al[mi][1] = Al[mr + 8][lr];
            ah[mi][2] = Ah[mr    ][4 + lr]; al[mi][2] = Al[mr    ][4 + lr];
            ah[mi][3] = Ah[mr + 8][4 + lr]; al[mi][3] = Al[mr + 8][4 + lr];
        }
        #pragma unroll
        for (int ni = 0; ni < NI; ni++) {
            int nr = w_n + ni*8 + lq;
            uint32_t bh[2], bl[2];
            bh[0] = Bh[nr][lr]; bh[1] = Bh[nr][4 + lr];
            bl[0] = Bl[nr][lr]; bl[1] = Bl[nr][4 + lr];
            mma16n8k16bf(acc[0][ni], ah[0], bh);
            mma16n8k16bf(acc[1][ni], ah[1], bh);
            mma16n8k16bf(acc[0][ni], ah[0], bl);
            mma16n8k16bf(acc[1][ni], ah[1], bl);
            mma16n8k16bf(acc[0][ni], al[0], bh);
            mma16n8k16bf(acc[1][ni], al[1], bh);
        }
        __syncthreads();
    }

    float* base = C;
    int csub = 0;
    bool isV = false;
    if (MODE == 1) {
        if (n0 < 512)       { base = Qo; csub = 0; }
        else if (n0 < 1024) { base = Ko; csub = 512; }
        else                { base = Vo; csub = 1024; isV = true; }
    } else if (MODE == 2) {
        base = splitz ? Qo : C;
    }
    #pragma unroll
    for (int mi = 0; mi < 2; mi++) {
        #pragma unroll
        for (int half = 0; half < 2; half++) {
            int r = w_m + mi*16 + lq + half*8;
            #pragma unroll
            for (int ni = 0; ni < NI; ni++) {
                float v0 = acc[mi][ni][half*2 + 0];
                float v1 = acc[mi][ni][half*2 + 1];
                int col = w_n + ni*8 + 2*lr;
                if (MODE == 2) {
                    float* cp = base + (size_t)(m0 + r) * N + n0 + col;
                    cp[0] = v0; cp[1] = v1;
                } else {
                    float* cp = base + (size_t)(m0 + r) * DD + (n0 - csub) + col;
                    if (isV) { cp[0] = f2tf32f(v0); cp[1] = f2tf32f(v1); }
                    else     { cp[0] = v0;          cp[1] = v1; }
                }
            }
        }
    }
}

// ============ tf32 mma.sync GEMM: pre-rounded inputs, raw bit copy ============
template<int MODE, int NI, bool CVTOUT>
__global__ void __launch_bounds__(256, 2)
tf32_gemm_kernel(const float* __restrict__ A, const float* __restrict__ Bt,
                 float* __restrict__ C, int K, int N, int ldA,
                 size_t sA, size_t sB, size_t sC,
                 const int* __restrict__ cnt, const int* __restrict__ off,
                 const int* __restrict__ tokl, const float* __restrict__ wtl) {
    constexpr int NT = NI * 16;
    __shared__ uint32_t As[128][36];
    __shared__ uint32_t Bs[NT][36];
    __shared__ int stok[128];
    __shared__ float swt[128];

    const int tid = threadIdx.x;
    const int n0 = blockIdx.x * NT;
    int m0 = 0, count = 0, t0 = 0, gbase = 0;

    if (MODE == 0) {
        m0 = blockIdx.y * 128;
        A += blockIdx.z * sA; Bt += blockIdx.z * sB; C += blockIdx.z * sC;
    } else {
        const int e = blockIdx.z;
        count = cnt[e];
        t0 = blockIdx.y * 128;
        if (t0 >= count) return;
        gbase = off[e] + t0;
        if (tid < 128) {
            bool ok = (t0 + tid) < count;
            stok[tid] = ok ? tokl[e*TT + t0 + tid] : -1;
            swt[tid]  = ok ? wtl [e*TT + t0 + tid] : 0.f;
        }
        Bt += (size_t)e * N * K;
        __syncthreads();
    }

    const int wid = tid >> 5, lid = tid & 31;
    const int w_m = (wid & 3) * 32, w_n = (wid >> 2) * (NI * 8);
    const int lq = lid >> 2, lr = lid & 3;
    const int row_l = tid >> 3, c4 = tid & 7;

    float acc[2][NI][4];
    #pragma unroll
    for (int i = 0; i < 2; i++)
        #pragma unroll
        for (int j = 0; j < NI; j++)
            #pragma unroll
            for (int l = 0; l < 4; l++) acc[i][j][l] = 0.f;

    float4 ra[4], rb[NI/2];
    auto LDG = [&](int t) {
        #pragma unroll
        for (int j = 0; j < 4; j++) {
            int row = row_l + j * 32;
            if (MODE == 0) {
                ra[j] = *(const float4*)(A + (size_t)(m0 + row) * ldA + t*32 + c4*4);
            } else {
                ra[j] = make_float4(0.f,0.f,0.f,0.f);
                if (t0 + row < count)
                    ra[j] = *(const float4*)(A + (size_t)(gbase + row) * K + t*32 + c4*4);
            }
        }
        #pragma unroll
        for (int j = 0; j < NI/2; j++) {
            int row = row_l + j * 32;
            rb[j] = *(const float4*)(Bt + (size_t)(n0 + row) * K + t*32 + c4*4);
        }
    };

    const int NK = K / 32;
    LDG(0);
    for (int i = 0; i < NK; i++) {
        #pragma unroll
        for (int j = 0; j < 4; j++) {
            int row = row_l + j * 32;
            uint32_t* ap = &As[row][c4*4];
            ap[0] = __float_as_uint(ra[j].x); ap[1] = __float_as_uint(ra[j].y);
            ap[2] = __float_as_uint(ra[j].z); ap[3] = __float_as_uint(ra[j].w);
        }
        #pragma unroll
        for (int j = 0; j < NI/2; j++) {
            int row = row_l + j * 32;
            uint32_t* bp = &Bs[row][c4*4];
            bp[0] = __float_as_uint(rb[j].x); bp[1] = __float_as_uint(rb[j].y);
            bp[2] = __float_as_uint(rb[j].z); bp[3] = __float_as_uint(rb[j].w);
        }
        __syncthreads();
        if (i + 1 < NK) LDG(i + 1);
        #pragma unroll
        for (int ks = 0; ks < 32; ks += 8) {
            uint32_t af[2][4], bf[NI][2];
            #pragma unroll
            for (int mi = 0; mi < 2; mi++) {
                int mr = w_m + mi*16 + lq;
                af[mi][0] = As[mr    ][ks + lr];
                af[mi][1] = As[mr + 8][ks + lr];
                af[mi][2] = As[mr    ][ks + 4 + lr];
                af[mi][3] = As[mr + 8][ks + 4 + lr];
            }
            #pragma unroll
            for (int ni = 0; ni < NI; ni++) {
                int nr = w_n + ni*8 + lq;
                bf[ni][0] = Bs[nr][ks + lr];
                bf[ni][1] = Bs[nr][ks + 4 + lr];
            }
            #pragma unroll
            for (int mi = 0; mi < 2; mi++)
                #pragma unroll
                for (int ni = 0; ni < NI; ni++)
                    mma16n8k8(acc[mi][ni], af[mi], bf[ni]);
        }
        __syncthreads();
    }

    #pragma unroll
    for (int mi = 0; mi < 2; mi++) {
        #pragma unroll
        for (int half = 0; half < 2; half++) {
            int r = w_m + mi*16 + lq + half*8;
            #pragma unroll
            for (int ni = 0; ni < NI; ni++) {
                float v0 = acc[mi][ni][half*2 + 0];
                float v1 = acc[mi][ni][half*2 + 1];
                int col = w_n + ni*8 + 2*lr;
                if (MODE == 0) {
                    float* cp = C + (size_t)(m0 + r) * N + n0 + col;
                    if (CVTOUT) { cp[0] = f2tf32f(v0); cp[1] = f2tf32f(v1); }
                    else        { cp[0] = v0;          cp[1] = v1; }
                } else {
                    if (t0 + r < count) {
                        int tk = stok[r];
                        float wt = swt[r];
                        float* op = C + (size_t)tk * DD + n0 + col;
                        atomicAdd(op + 0, wt * v0);
                        atomicAdd(op + 1, wt * v1);
                    }
                }
            }
        }
    }
}

// ============ fused MoE up: G = sin(xm@W1t^T) * (xm@W3t^T) ============
// Tile 128x64 (NI=4): 2 CTAs/SM. Static smem.
__global__ void __launch_bounds__(256, 2)
moe_up_fused_kernel(const float* __restrict__ xm,
                    const float* __restrict__ B1t, const float* __restrict__ B3t,
                    float* __restrict__ G,
                    const int* __restrict__ cnt, const int* __restrict__ off,
                    const int* __restrict__ tokl) {
    __shared__ uint32_t As[128][36];
    __shared__ uint32_t B1s[64][36];
    __shared__ uint32_t B3s[64][36];
    __shared__ int stok[128];

    const int tid = threadIdx.x;
    const int e = blockIdx.z;
    const int count = cnt[e];
    const int t0 = blockIdx.y * 128;
    if (t0 >= count) return;
    const int n0 = blockIdx.x * 64;
    const int gbase = off[e] + t0;
    if (tid < 128)
        stok[tid] = (t0 + tid < count) ? tokl[e*TT + t0 + tid] : -1;
    B1t += (size_t)e * HH * DD;
    B3t += (size_t)e * HH * DD;
    __syncthreads();

    const int wid = tid >> 5, lid = tid & 31;
    const int w_m = (wid & 3) * 32, w_n = (wid >> 2) * 32;
    const int lq = lid >> 2, lr = lid & 3;
    const int row_l = tid >> 3, c4 = tid & 7;

    float acc1[2][4][4], acc3[2][4][4];
    #pragma unroll
    for (int i = 0; i < 2; i++)
        #pragma unroll
        for (int j = 0; j < 4; j++)
            #pragma unroll
            for (int l = 0; l < 4; l++) { acc1[i][j][l] = 0.f; acc3[i][j][l] = 0.f; }

    float4 ra[4], rb1[2], rb3[2];
    auto LDG = [&](int t) {
        #pragma unroll
        for (int j = 0; j < 4; j++) {
            int row = row_l + j * 32;
            int tk = stok[row];
            ra[j] = make_float4(0.f,0.f,0.f,0.f);
            if (tk >= 0)
                ra[j] = *(const float4*)(xm + (size_t)tk * DD + t*32 + c4*4);
        }
        #pragma unroll
        for (int j = 0; j < 2; j++) {
            int row = row_l + j * 32;
            rb1[j] = *(const float4*)(B1t + (size_t)(n0 + row) * DD + t*32 + c4*4);
            rb3[j] = *(const float4*)(B3t + (size_t)(n0 + row) * DD + t*32 + c4*4);
        }
    };

    const int NK = DD / 32;
    LDG(0);
    for (int i = 0; i < NK; i++) {
        #pragma unroll
        for (int j = 0; j < 4; j++) {
            int row = row_l + j * 32;
            uint32_t* ap = &As[row][c4*4];
            ap[0] = f2tf32(ra[j].x); ap[1] = f2tf32(ra[j].y);
            ap[2] = f2tf32(ra[j].z); ap[3] = f2tf32(ra[j].w);
        }
        #pragma unroll
        for (int j = 0; j < 2; j++) {
            int row = row_l + j * 32;
            uint32_t* b1p = &B1s[row][c4*4];
            uint32_t* b3p = &B3s[row][c4*4];
            b1p[0] = __float_as_uint(rb1[j].x); b1p[1] = __float_as_uint(rb1[j].y);
            b1p[2] = __float_as_uint(rb1[j].z); b1p[3] = __float_as_uint(rb1[j].w);
            b3p[0] = __float_as_uint(rb3[j].x); b3p[1] = __float_as_uint(rb3[j].y);
            b3p[2] = __float_as_uint(rb3[j].z); b3p[3] = __float_as_uint(rb3[j].w);
        }
        __syncthreads();
        if (i + 1 < NK) LDG(i + 1);
        #pragma unroll
        for (int ks = 0; ks < 32; ks += 8) {
            uint32_t af[2][4];
            #pragma unroll
            for (int mi = 0; mi < 2; mi++) {
                int mr = w_m + mi*16 + lq;
                af[mi][0] = As[mr    ][ks + lr];
                af[mi][1] = As[mr + 8][ks + lr];
                af[mi][2] = As[mr    ][ks + 4 + lr];
                af[mi][3] = As[mr + 8][ks + 4 + lr];
            }
            #pragma unroll
            for (int ni = 0; ni < 4; ni++) {
                int nr = w_n + ni*8 + lq;
                uint32_t b1[2], b3[2];
                b1[0] = B1s[nr][ks + lr]; b1[1] = B1s[nr][ks + 4 + lr];
                b3[0] = B3s[nr][ks + lr]; b3[1] = B3s[nr][ks + 4 + lr];
                mma16n8k8(acc1[0][ni], af[0], b1);
                mma16n8k8(acc1[1][ni], af[1], b1);
                mma16n8k8(acc3[0][ni], af[0], b3);
                mma16n8k8(acc3[1][ni], af[1], b3);
            }
        }
        __syncthreads();
    }

    #pragma unroll
    for (int mi = 0; mi < 2; mi++) {
        #pragma unroll
        for (int half = 0; half < 2; half++) {
            int r = w_m + mi*16 + lq + half*8;
            if (t0 + r < count) {
                float* gp = G + (size_t)(gbase + r) * HH + n0;
                #pragma unroll
                for (int ni = 0; ni < 4; ni++) {
                    int col = w_n + ni*8 + 2*lr;
                    gp[col + 0] = f2tf32f(sinf(acc1[mi][ni][half*2 + 0]) * acc3[mi][ni][half*2 + 0]);
                    gp[col + 1] = f2tf32f(sinf(acc1[mi][ni][half*2 + 1]) * acc3[mi][ni][half*2 + 1]);
                }
            }
        }
    }
}

__global__ void aux_kernel(const float* __restrict__ probs, float* __restrict__ out, int out_size) {
    __shared__ float red[256];
    int tid = threadIdx.x;
    float s = 0.f;
    for (int idx = tid; idx < SS*EE; idx += 256) {
        int srow = idx >> 3, e = idx & 7;
        float a = 0.f;
        #pragma unroll
        for (int b = 0; b < BB; b++)
            a += probs[(size_t)((b << 10) + srow)*EE + e];
        a *= 0.25f;
        float d = (1.f / EE) - a;
        s += d * d;
    }
    red[tid] = s; __syncthreads();
    for (int o = 128; o; o >>= 1) { if (tid < o) red[tid] += red[tid + o]; __syncthreads(); }
    if (!tid && out_size > TT*DD) out[TT*DD] = red[0];
}

// ---------------- host launcher ----------------
extern "C" void kernel_launch(void* const* d_in, const int* in_sizes, int n_in,
                              void* d_out, int out_size) {
    const float* x     = (const float*)d_in[0];
    const float* c     = (const float*)d_in[1];
    const float* W_ada = (const float*)d_in[2];
    const float* b_ada = (const float*)d_in[3];
    const float* Wq    = (const float*)d_in[4];
    const float* Wk    = (const float*)d_in[5];
    const float* Wv    = (const float*)d_in[6];
    const float* Wo    = (const float*)d_in[7];
    const float* qn_w  = (const float*)d_in[8];
    const float* qn_b  = (const float*)d_in[9];
    const float* kn_w  = (const float*)d_in[10];
    const float* kn_b  = (const float*)d_in[11];
    const float* an_w  = (const float*)d_in[12];
    const float* an_b  = (const float*)d_in[13];
    const float* fn_w  = (const float*)d_in[14];
    const float* fn_b  = (const float*)d_in[15];
    const float* Wr    = (const float*)d_in[16];
    const float* br    = (const float*)d_in[17];
    const float* W1    = (const float*)d_in[18];
    const float* W2    = (const float*)d_in[19];
    const float* W3    = (const float*)d_in[20];
    float* out = (float*)d_out;

    float* buf; cudaGetSymbolAddress((void**)&buf, g_buf);
    int* ibuf;  cudaGetSymbolAddress((void**)&ibuf, g_ibuf);

    float* mods   = buf + OF_MODS;
    float* h      = buf + OF_H;
    float* q      = buf + OF_Q;
    float* k      = buf + OF_K;
    float* v      = buf + OF_V;
    float* scores = buf + OF_SC;
    float* attn   = buf + OF_AT;        // also scores split-1 partial (dead until step 7)
    float* attnO  = buf + OF_AO;
    float* xm     = buf + OF_XM;
    float* logits = buf + OF_LG;
    float* probs  = buf + OF_PR;
    float* nrm    = buf + OF_NRM;
    float* wtl    = buf + OF_WT;
    float2* qst   = (float2*)(buf + OF_QS);
    float2* kst   = (float2*)(buf + OF_KS);
    float* G      = buf + OF_G;
    float* w1t    = buf + OF_W1T;
    float* w3t    = buf + OF_W3T;
    float* w2t    = buf + OF_W2T;
    float* wqkvt  = buf + OF_WQKVT;
    float* wot    = buf + OF_WOT;
    float* qT     = buf + OF_QT;
    float* kT     = buf + OF_KT;
    int* cnt  = ibuf + IOF_CNT;
    int* off  = ibuf + IOF_OFF;
    int* tokl = ibuf + IOF_TOK;

    // 0. zero out + counters; weight transposes (pre-rounded where tf32-exclusive)
    zero_kernel<<<(TT*DD + 255)/256, 256>>>(out, cnt);
    transpose13_kernel<<<dim3(HH/32, DD/32, EE), dim3(32,8)>>>(W1, W3, w1t, w3t, DD, HH);
    transpose_kernel<true><<<dim3(DD/32, HH/32, EE), dim3(32,8)>>>(W2, w2t, HH, DD);
    transpose4_kernel<<<dim3(DD/32, DD/32, 4), dim3(32,8)>>>(Wq, Wk, Wv, Wo, wqkvt, wot);

    // 1. adaLN mods
    mods_kernel<<<dim3(BB, SIXD/256), 256>>>(c, W_ada, b_ada, mods);

    // 2. h = modulate(LN(x; an), sh_msa, sc_msa)
    ln_mod_kernel<false><<<TT/2, 256>>>(x, nullptr, h, an_w, an_b, mods, 0, DD);

    // 3. fused QKV projection — bf16 3-pass; V output pre-rounded to tf32
    b163_gemm_kernel<1,8><<<dim3(3*DD/128, TT/128), 256>>>(h, wqkvt, nullptr, DD, 3*DD, DD,
                                                           0,0,0, q, k, v);

    // 4. LN stats for q & k (single launch), then fused LN-apply + transpose
    row_stats_qk_kernel<<<TT, 256>>>(q, k, qst, kst);
    transpose_ln_kernel<<<dim3(DD/32, SS/32, 2*BB), dim3(32,8)>>>(q, k, qT, kT, qst, kst,
                                                                  qn_w, qn_b, kn_w, kn_b);

    // 5. scores partials: split-K=2 over S, plain stores into scores (split 0)
    //    and attn buffer (split 1) — 256 blocks, no atomics.
    b163_gemm_kernel<2,4><<<dim3(DD/64, DD/128, 2*BB), 256>>>(qT, kT, scores, SS/2, DD, SS,
                                                              (size_t)DD*SS, (size_t)DD*SS,
                                                              (size_t)DD*DD,
                                                              attn, nullptr, nullptr);

    // 6. softmax rows of 512 (reads p0+p1, shfl; output pre-rounded to tf32)
    softmax512_kernel<<<BB*DD/2, 256>>>(scores, attn);

    // 7. attn = v @ A^T — tf32, output pre-rounded (attn buffer now reused as output)
    tf32_gemm_kernel<0,4,true><<<dim3(DD/64, SS/128, BB), 256>>>(v, scores, attn, DD, DD, DD,
                                                                 (size_t)SS*DD, (size_t)DD*DD,
                                                                 (size_t)SS*DD, 0,0,0,0);

    // 8. attnO = attn @ Wo — tf32, fp32 output
    tf32_gemm_kernel<0,4,false><<<dim3(DD/64, TT/128, 1), 256>>>(attn, wot, attnO, DD, DD, DD,
                                                                 0,0,0, 0,0,0,0);

    // 9+10. xm = modulate(LN(x + g_msa*attnO; fn), sh_mlp, sc_mlp)
    ln_mod_kernel<true><<<TT/2, 256>>>(x, attnO, xm, fn_w, fn_b, mods, 3*DD, 4*DD);

    // 11-14. routing
    logits_kernel<<<TT, 256>>>(xm, Wr, br, logits);
    nrm_kernel<<<BB*EE, 256>>>(logits, nrm);
    route_kernel<<<TT/128, 128>>>(logits, nrm, probs, cnt, tokl, wtl);
    offsets_kernel<<<1, 32>>>(cnt, off);

    // 15. fused MoE up: G = sin(xm@W1^T) * (xm@W3^T) — 128x64 tiles, 2 CTAs/SM
    moe_up_fused_kernel<<<dim3(HH/64, TT/128, EE), 256>>>(xm, w1t, w3t, G, cnt, off, tokl);

    // 16. MoE down: out += wt * (G @ W2^T)
    tf32_gemm_kernel<3,8,false><<<dim3(DD/128, TT/128, EE), 256>>>(G, w2t, out, HH, DD, HH,
                                                                   0,0,0, cnt, off, tokl, wtl);

    // 17. aux loss
    aux_kernel<<<1, 256>>>(probs, out, out_size);
}